// round 14
// baseline (speedup 1.0000x reference)
#include <cuda_runtime.h>
#include <cuda_bf16.h>
#include <cuda_fp16.h>
#include <math.h>

typedef unsigned u32;

#define B_  32
#define TQ_ 1024
#define TK_ 1024
#define D_  64
#define STRD 72   // smem row stride in 2B elems (64 data + 8 pad): conflict-free frags
#define VSTR 68   // fp32 tile row stride (conflict-free for split reads)

// scratch: fp16 scores/probs, 2-part rowsums, pos_v overlap accumulator,
// precomputed bf16 hi/lo Q,K
static __device__ __half g_S[(size_t)B_ * TQ_ * TK_];
static __device__ __half g_P[(size_t)B_ * TQ_ * TK_];
static __device__ float  g_psum[(size_t)B_ * TQ_ * 2];
static __device__ float  g_O2[(size_t)B_ * TQ_ * D_];
static __device__ __nv_bfloat16 g_Qh[(size_t)B_ * TQ_ * D_];
static __device__ __nv_bfloat16 g_Ql[(size_t)B_ * TQ_ * D_];
static __device__ __nv_bfloat16 g_Kh[(size_t)B_ * TK_ * D_];
static __device__ __nv_bfloat16 g_Kl[(size_t)B_ * TK_ * D_];

// ---- mma helpers ----------------------------------------------------------
__device__ __forceinline__ void mma_bf16(float c[4], u32 a0, u32 a1, u32 a2, u32 a3,
                                         u32 b0, u32 b1)
{
    asm volatile(
        "mma.sync.aligned.m16n8k16.row.col.f32.bf16.bf16.f32 "
        "{%0,%1,%2,%3},{%4,%5,%6,%7},{%8,%9},{%0,%1,%2,%3};\n"
        : "+f"(c[0]), "+f"(c[1]), "+f"(c[2]), "+f"(c[3])
        : "r"(a0), "r"(a1), "r"(a2), "r"(a3), "r"(b0), "r"(b1));
}
__device__ __forceinline__ void mma_f16(float c[4], u32 a0, u32 a1, u32 a2, u32 a3,
                                        u32 b0, u32 b1)
{
    asm volatile(
        "mma.sync.aligned.m16n8k16.row.col.f32.f16.f16.f32 "
        "{%0,%1,%2,%3},{%4,%5,%6,%7},{%8,%9},{%0,%1,%2,%3};\n"
        : "+f"(c[0]), "+f"(c[1]), "+f"(c[2]), "+f"(c[3])
        : "r"(a0), "r"(a1), "r"(a2), "r"(a3), "r"(b0), "r"(b1));
}

__device__ __forceinline__ u32 cvt2bf(float hi, float lo) {
    u32 r;
    asm("cvt.rn.bf16x2.f32 %0,%1,%2;" : "=r"(r) : "f"(hi), "f"(lo));
    return r;
}
// bf16 hi/lo split (x0 -> low half, x1 -> high half)
__device__ __forceinline__ void split2(float x0, float x1, u32& h, u32& l) {
    h = cvt2bf(x1, x0);
    float h0 = __uint_as_float(h << 16);
    float h1 = __uint_as_float(h & 0xffff0000u);
    l = cvt2bf(x1 - h1, x0 - h0);
}
// fp16 hi/lo split
__device__ __forceinline__ void split2h(float x0, float x1, u32& h, u32& l) {
    __half2 hh = __floats2half2_rn(x0, x1);
    h = *(u32*)&hh;
    float2 hf = __half22float2(hh);
    __half2 ll = __floats2half2_rn(x0 - hf.x, x1 - hf.y);
    l = *(u32*)&ll;
}

// ---- cp.async helpers -----------------------------------------------------
__device__ __forceinline__ void cp16(void* dst_smem, const void* src) {
    u32 d = (u32)__cvta_generic_to_shared(dst_smem);
    asm volatile("cp.async.cg.shared.global [%0], [%1], 16;\n" :: "r"(d), "l"(src));
}
#define CP_COMMIT() asm volatile("cp.async.commit_group;\n" ::)
#define CP_WAIT1()  asm volatile("cp.async.wait_group 1;\n" ::)
#define CP_WAIT0()  asm volatile("cp.async.wait_group 0;\n" ::)

// ---------------------------------------------------------------------------
// Kernel P0: precompute bf16 hi/lo for Q and K (row-major, same layout)
// ---------------------------------------------------------------------------
extern "C" __global__ void __launch_bounds__(256)
prep_qk_kernel(const float* __restrict__ Q, const float* __restrict__ K)
{
    size_t idx = (size_t)blockIdx.x * 256 + threadIdx.x;
    float4 v = ((const float4*)Q)[idx];
    u32 h0, l0, h1, l1;
    split2(v.x, v.y, h0, l0); split2(v.z, v.w, h1, l1);
    ((uint2*)g_Qh)[idx] = make_uint2(h0, h1);
    ((uint2*)g_Ql)[idx] = make_uint2(l0, l1);
    float4 w = ((const float4*)K)[idx];
    split2(w.x, w.y, h0, l0); split2(w.z, w.w, h1, l1);
    ((uint2*)g_Kh)[idx] = make_uint2(h0, h1);
    ((uint2*)g_Kl)[idx] = make_uint2(l0, l1);
}

// ---------------------------------------------------------------------------
// Kernel A: S[b,q,k] = Q[b,q,:]·K[b,k,:] (unscaled, fp16 out). bf16x3 MMA.
// Block tile 128(q) x 64(k); warps 4(m) x 2(n); dynamic smem (55.3 KB).
// ---------------------------------------------------------------------------
#define QK_A_H   (128 * STRD)
#define QK_B_H   (64 * STRD)
#define QK_SMEM  ((2 * QK_A_H + 2 * QK_B_H) * 2)

extern "C" __global__ void __launch_bounds__(256)
qk_kernel()
{
    extern __shared__ char dynq[];
    __half* Ah = (__half*)dynq;                 // [128][STRD] (bf16 bits)
    __half* Al = Ah + QK_A_H;
    __half* Bh = Al + QK_A_H;                   // [64][STRD]
    __half* Bl = Bh + QK_B_H;

    const int bz = blockIdx.z;
    const int qt = blockIdx.y * 128;
    const int kt = blockIdx.x * 64;
    __half* Sb = g_S + (size_t)bz * TQ_ * TK_;

    const int tid = threadIdx.x;
    {
        const __nv_bfloat16* qh = g_Qh + ((size_t)bz * TQ_ + qt) * D_;
        const __nv_bfloat16* ql = g_Ql + ((size_t)bz * TQ_ + qt) * D_;
#pragma unroll
        for (int i = 0; i < 2; i++) {
            int idx = tid + i * 256;
            int row = idx >> 2;
            int c8  = (idx & 3) * 16;
            cp16(Ah + row * STRD + c8,     qh + row * D_ + c8);
            cp16(Ah + row * STRD + c8 + 8, qh + row * D_ + c8 + 8);
            cp16(Al + row * STRD + c8,     ql + row * D_ + c8);
            cp16(Al + row * STRD + c8 + 8, ql + row * D_ + c8 + 8);
        }
        const __nv_bfloat16* kh = g_Kh + ((size_t)bz * TK_ + kt) * D_;
        const __nv_bfloat16* kl = g_Kl + ((size_t)bz * TK_ + kt) * D_;
        {
            int row = tid >> 2;
            int c8  = (tid & 3) * 16;
            cp16(Bh + row * STRD + c8,     kh + row * D_ + c8);
            cp16(Bh + row * STRD + c8 + 8, kh + row * D_ + c8 + 8);
            cp16(Bl + row * STRD + c8,     kl + row * D_ + c8);
            cp16(Bl + row * STRD + c8 + 8, kl + row * D_ + c8 + 8);
        }
    }
    CP_COMMIT();
    CP_WAIT0();
    __syncthreads();

    const int wid = tid >> 5, lane = tid & 31;
    const int g = lane >> 2, tg = lane & 3;
    const int wm = (wid >> 1) * 32;
    const int wn = (wid & 1) * 32;

    float c[2][4][4] = {};

#pragma unroll
    for (int k0 = 0; k0 < 64; k0 += 16) {
        u32 ah[2][4], al[2][4], bh[4][2], bl[4][2];
#pragma unroll
        for (int mi = 0; mi < 2; mi++) {
            const __half* ph = Ah + (wm + mi * 16 + g) * STRD + k0 + 2 * tg;
            ah[mi][0] = *(const u32*)(ph);
            ah[mi][1] = *(const u32*)(ph + 8 * STRD);
            ah[mi][2] = *(const u32*)(ph + 8);
            ah[mi][3] = *(const u32*)(ph + 8 * STRD + 8);
            const __half* pl = Al + (wm + mi * 16 + g) * STRD + k0 + 2 * tg;
            al[mi][0] = *(const u32*)(pl);
            al[mi][1] = *(const u32*)(pl + 8 * STRD);
            al[mi][2] = *(const u32*)(pl + 8);
            al[mi][3] = *(const u32*)(pl + 8 * STRD + 8);
        }
#pragma unroll
        for (int ni = 0; ni < 4; ni++) {
            const __half* ph = Bh + (wn + ni * 8 + g) * STRD + k0 + 2 * tg;
            bh[ni][0] = *(const u32*)(ph);
            bh[ni][1] = *(const u32*)(ph + 8);
            const __half* pl = Bl + (wn + ni * 8 + g) * STRD + k0 + 2 * tg;
            bl[ni][0] = *(const u32*)(pl);
            bl[ni][1] = *(const u32*)(pl + 8);
        }
#pragma unroll
        for (int mi = 0; mi < 2; mi++)
#pragma unroll
            for (int ni = 0; ni < 4; ni++) {
                mma_bf16(c[mi][ni], ah[mi][0], ah[mi][1], ah[mi][2], ah[mi][3],
                         bh[ni][0], bh[ni][1]);
                mma_bf16(c[mi][ni], al[mi][0], al[mi][1], al[mi][2], al[mi][3],
                         bh[ni][0], bh[ni][1]);
                mma_bf16(c[mi][ni], ah[mi][0], ah[mi][1], ah[mi][2], ah[mi][3],
                         bl[ni][0], bl[ni][1]);
            }
    }

    __syncthreads();
    __half* Es = Ah;   // [128][STRD]
#pragma unroll
    for (int mi = 0; mi < 2; mi++)
#pragma unroll
        for (int ni = 0; ni < 4; ni++) {
            int ml = wm + mi * 16 + g;
            int nl = wn + ni * 8 + 2 * tg;
            *(__half2*)&Es[ml * STRD + nl] =
                __floats2half2_rn(c[mi][ni][0], c[mi][ni][1]);
            *(__half2*)&Es[(ml + 8) * STRD + nl] =
                __floats2half2_rn(c[mi][ni][2], c[mi][ni][3]);
        }
    __syncthreads();
#pragma unroll
    for (int i = 0; i < 4; i++) {
        int idx = tid + i * 256;
        int row = idx >> 3;
        int c8  = (idx & 7) * 8;
        uint4 v = *(const uint4*)&Es[row * STRD + c8];
        *(uint4*)&Sb[(size_t)(qt + row) * TK_ + kt + c8] = v;
    }
}

// ---------------------------------------------------------------------------
// Kernel B: P(fp16) = exp(mask((S + Q·pos_k)/8)); streaming per-q kernel.
// grid (2, 1024): (k-half, q). 8 chunks of 64 k, 2-stage cp.async pipeline.
// Per chunk: MMA -> stage accum into consumed buffer -> coalesced S/exp/P
// pass + segmented rowsum accumulated in smem. Emits 1 partial per half.
// ---------------------------------------------------------------------------
__device__ __forceinline__ int bswz(int n, int c) {
    return n * 64 + ((((c >> 2) ^ (n & 7)) << 2) | (c & 3));
}
#define CST2 68

extern "C" __global__ void __launch_bounds__(256)
posk_kernel(const float* __restrict__ PK, const int* __restrict__ VL)
{
    const int half = blockIdx.x;
    const int q    = blockIdx.y;
    const int kt0  = half * 512;

    __shared__ __nv_bfloat16 Ah[32][STRD], Al[32][STRD];
    __shared__ float Bst[2][64 * 64];    // pos_k chunks fp32, swizzled (16KB ea)
    __shared__ float rsum_acc[32];
    __shared__ int vls[B_];

    const int tid = threadIdx.x;
    const float* PKq = PK + (size_t)q * TK_ * D_;

    auto load_chunk = [&](int s, int kt) {
#pragma unroll
        for (int i = 0; i < 4; i++) {        // 1024 x 16B over 64x64 fp32
            int idx = tid + i * 256;
            int row = idx >> 4;
            int c4  = idx & 15;
            cp16(&Bst[s][row * 64 + ((c4 ^ (row & 7)) << 2)],
                 PKq + (size_t)(kt + row) * D_ + c4 * 4);
        }
    };

    // prologue: Q tiles + chunk0 in group0; chunk1 in group1
    {
        int row = tid >> 3;
        int c8  = (tid & 7) * 8;
        cp16(&Ah[row][c8], g_Qh + ((size_t)row * TQ_ + q) * D_ + c8);
        cp16(&Al[row][c8], g_Ql + ((size_t)row * TQ_ + q) * D_ + c8);
    }
    load_chunk(0, kt0);
    CP_COMMIT();
    load_chunk(1, kt0 + 64);
    CP_COMMIT();
    if (tid < B_) { vls[tid] = VL[tid]; rsum_acc[tid] = 0.f; }

    const int wid = tid >> 5, lane = tid & 31;
    const int g = lane >> 2, tg = lane & 3;
    const int wn = wid * 8;

    for (int ci = 0; ci < 8; ci++) {
        const int s  = ci & 1;
        const int kt = kt0 + ci * 64;
        if (ci < 7) { CP_WAIT1(); } else { CP_WAIT0(); }
        __syncthreads();

        // MMA: M=32(batch) x N=64(k-chunk), Kdim=64, bf16x3
        float c[2][4] = {};
        const float* Bc = Bst[s];
#pragma unroll
        for (int k0 = 0; k0 < 64; k0 += 16) {
            u32 ah[2][4], al[2][4], bh[2], bl[2];
#pragma unroll
            for (int mi = 0; mi < 2; mi++) {
                const __nv_bfloat16* ph = &Ah[mi * 16 + g][k0 + 2 * tg];
                ah[mi][0] = *(const u32*)(ph);
                ah[mi][1] = *(const u32*)(ph + 8 * STRD);
                ah[mi][2] = *(const u32*)(ph + 8);
                ah[mi][3] = *(const u32*)(ph + 8 * STRD + 8);
                const __nv_bfloat16* pl = &Al[mi * 16 + g][k0 + 2 * tg];
                al[mi][0] = *(const u32*)(pl);
                al[mi][1] = *(const u32*)(pl + 8 * STRD);
                al[mi][2] = *(const u32*)(pl + 8);
                al[mi][3] = *(const u32*)(pl + 8 * STRD + 8);
            }
            {
                const int n = wn + g;
                float2 v0 = *(const float2*)&Bc[bswz(n, k0 + 2 * tg)];
                split2(v0.x, v0.y, bh[0], bl[0]);
                float2 v1 = *(const float2*)&Bc[bswz(n, k0 + 2 * tg + 8)];
                split2(v1.x, v1.y, bh[1], bl[1]);
            }
#pragma unroll
            for (int mi = 0; mi < 2; mi++) {
                mma_bf16(c[mi], ah[mi][0], ah[mi][1], ah[mi][2], ah[mi][3],
                         bh[0], bh[1]);
                mma_bf16(c[mi], al[mi][0], al[mi][1], al[mi][2], al[mi][3],
                         bh[0], bh[1]);
                mma_bf16(c[mi], ah[mi][0], ah[mi][1], ah[mi][2], ah[mi][3],
                         bl[0], bl[1]);
            }
        }
        __syncthreads();                       // all MMA reads of stage s done

        // stage accumulators into the consumed buffer
        float* Cs = Bst[s];                    // [32][CST2] region
#pragma unroll
        for (int mi = 0; mi < 2; mi++) {
            const int b0 = mi * 16 + g;
            const int col = wn + 2 * tg;
            *(float2*)&Cs[b0 * CST2 + col]       = make_float2(c[mi][0], c[mi][1]);
            *(float2*)&Cs[(b0 + 8) * CST2 + col] = make_float2(c[mi][2], c[mi][3]);
        }
        __syncthreads();

        // coalesced S-read / exp / P-write (128B per row), segmented rowsum
        {
            int row = tid >> 3;
            int c8  = (tid & 7) * 8;
            uint4 sv = *(const uint4*)&g_S[((size_t)row * TQ_ + q) * TK_ + kt + c8];
            const int vl = vls[row];
            uint4 out;
            float sum8 = 0.f;
#pragma unroll
            for (int j = 0; j < 4; j++) {
                u32 sraw = ((const u32*)&sv)[j];
                float2 sc = __half22float2(*(__half2*)&sraw);
                float cva = Cs[row * CST2 + c8 + 2 * j];
                float cvb = Cs[row * CST2 + c8 + 2 * j + 1];
                int col = kt + c8 + 2 * j;
                float e0 = (col     < vl) ? __expf((sc.x + cva) * 0.125f) : 0.f;
                float e1 = (col + 1 < vl) ? __expf((sc.y + cvb) * 0.125f) : 0.f;
                __half2 hp = __floats2half2_rn(e0, e1);
                ((u32*)&out)[j] = *(u32*)&hp;
                float2 er = __half22float2(hp);
                sum8 += er.x + er.y;
            }
            *(uint4*)&g_P[((size_t)row * TQ_ + q) * TK_ + kt + c8] = out;
            float v = sum8;
            v += __shfl_xor_sync(0xffffffffu, v, 1);
            v += __shfl_xor_sync(0xffffffffu, v, 2);
            v += __shfl_xor_sync(0xffffffffu, v, 4);
            if ((tid & 7) == 0) rsum_acc[row] += v;
        }
        __syncthreads();                       // epilogue done before refill

        if (ci + 2 < 8) { load_chunk(s, kt0 + (ci + 2) * 64); CP_COMMIT(); }
    }

    if (tid < B_)
        g_psum[((size_t)tid * TQ_ + q) * 2 + half] = rsum_acc[tid];
}

// ---------------------------------------------------------------------------
// Kernel C: MERGED pv + posv. grid 1536, interleaved 1:2.
// pv writes Out; posv writes g_O2 (race-free). Dynamic smem = 53.5 KB.
// ---------------------------------------------------------------------------
#define PV_AH_BYTES (2 * 64 * STRD * 2)
#define PV_VS_BYTES (2 * 64 * VSTR * 4)
#define PV_SMEM     (PV_AH_BYTES + PV_VS_BYTES + 64 * 4)

extern "C" __global__ void __launch_bounds__(256)
pvposv_kernel(const float* __restrict__ V, const float* __restrict__ PV,
              float* __restrict__ Out)
{
    extern __shared__ char dynbuf[];
    const int bid = blockIdx.x;
    const int third = bid / 3;
    const int rem   = bid % 3;
    const int tid = threadIdx.x;
    const int wid = tid >> 5, lane = tid & 31;
    const int g = lane >> 2, tg = lane & 3;

    if (rem == 0) {
        // ---------------- pv path ------------------------------------------
        __half* AhB  = (__half*)dynbuf;                       // [2][64][STRD]
        float*  VsB  = (float*)(dynbuf + PV_AH_BYTES);        // [2][64][VSTR]
        float*  invs = (float*)(dynbuf + PV_AH_BYTES + PV_VS_BYTES);

        const int bz = third >> 4;
        const int qt = (third & 15) * 64;
        const float* Vb = V + (size_t)bz * TK_ * D_;
        const __half* Pb = g_P + (size_t)bz * TQ_ * TK_;

        if (tid < 64) {
            float2 p = *(const float2*)&g_psum[((size_t)bz * TQ_ + qt + tid) * 2];
            invs[tid] = 1.0f / (p.x + p.y);
        }

        auto load_stage = [&](int s, int kt) {
            __half* A = AhB + s * 64 * STRD;
            float*  Vt = VsB + s * 64 * VSTR;
#pragma unroll
            for (int i = 0; i < 2; i++) {
                int idx = tid + i * 256;
                int r  = idx >> 3;
                int kc = (idx & 7) * 8;
                cp16(A + r * STRD + kc, Pb + (size_t)(qt + r) * TK_ + kt + kc);
            }
#pragma unroll
            for (int i = 0; i < 4; i++) {
                int idx = tid + i * 256;
                int k  = idx >> 4;
                int dc = (idx & 15) * 4;
                cp16(Vt + k * VSTR + dc, Vb + (size_t)(kt + k) * D_ + dc);
            }
            CP_COMMIT();
        };

        const int wm = (wid >> 2) * 32;
        const int wn = (wid & 3) * 16;

        float c[2][2][4] = {};

        load_stage(0, 0);
        for (int ci = 0; ci < 16; ci++) {
            const int s = ci & 1;
            if (ci < 15) { load_stage(s ^ 1, (ci + 1) * 64); CP_WAIT1(); }
            else         { CP_WAIT0(); }
            __syncthreads();

            const __half* A = AhB + s * 64 * STRD;
            const float*  Vt = VsB + s * 64 * VSTR;
#pragma unroll
            for (int k0 = 0; k0 < 64; k0 += 16) {
                u32 a[2][4], bh[2][2], bl[2][2];
#pragma unroll
                for (int mi = 0; mi < 2; mi++) {
                    const __half* ph = A + (wm + mi * 16 + g) * STRD + k0 + 2 * tg;
                    a[mi][0] = *(const u32*)(ph);
                    a[mi][1] = *(const u32*)(ph + 8 * STRD);
                    a[mi][2] = *(const u32*)(ph + 8);
                    a[mi][3] = *(const u32*)(ph + 8 * STRD + 8);
                }
#pragma unroll
                for (int ni = 0; ni < 2; ni++) {
                    const int n = wn + ni * 8 + g;
                    const int kb = k0 + 2 * tg;
                    split2h(Vt[kb * VSTR + n],       Vt[(kb + 1) * VSTR + n], bh[ni][0], bl[ni][0]);
                    split2h(Vt[(kb + 8) * VSTR + n], Vt[(kb + 9) * VSTR + n], bh[ni][1], bl[ni][1]);
                }
#pragma unroll
                for (int mi = 0; mi < 2; mi++)
#pragma unroll
                    for (int ni = 0; ni < 2; ni++) {
                        mma_f16(c[mi][ni], a[mi][0], a[mi][1], a[mi][2], a[mi][3],
                                bh[ni][0], bh[ni][1]);
                        mma_f16(c[mi][ni], a[mi][0], a[mi][1], a[mi][2], a[mi][3],
                                bl[ni][0], bl[ni][1]);
                    }
            }
            __syncthreads();
        }

#pragma unroll
        for (int mi = 0; mi < 2; mi++)
#pragma unroll
            for (int ni = 0; ni < 2; ni++) {
                int m = wm + mi * 16 + g;
                int n = wn + ni * 8 + 2 * tg;
                float inv0 = invs[m], inv1 = invs[m + 8];
                float* d0 = Out + ((size_t)bz * TQ_ + qt + m) * D_ + n;
                *(float2*)d0 = make_float2(c[mi][ni][0] * inv0, c[mi][ni][1] * inv0);
                float* d1 = Out + ((size_t)bz * TQ_ + qt + m + 8) * D_ + n;
                *(float2*)d1 = make_float2(c[mi][ni][2] * inv1, c[mi][ni][3] * inv1);
            }
    } else {
        // ---------------- posv path ----------------------------------------
        const int q = third * 2 + (rem - 1);

        __half* Ahs  = (__half*)dynbuf;                       // [2][32][STRD]
        float*  PVs  = (float*)(dynbuf + 2 * 32 * STRD * 2);  // [2][64][VSTR]
        float*  invs = (float*)(dynbuf + 2 * 32 * STRD * 2 + 2 * 64 * VSTR * 4);

        if (tid < B_) {
            float2 p = *(const float2*)&g_psum[((size_t)tid * TQ_ + q) * 2];
            invs[tid] = 1.0f / (p.x + p.y);
        }

        auto load_stage = [&](int s, int kt) {
            {
                int bb = tid >> 3;
                int kc = (tid & 7) * 8;
                cp16(Ahs + (s * 32 + bb) * STRD + kc,
                     g_P + ((size_t)bb * TQ_ + q) * TK_ + kt + kc);
            }
            const float* PVq = PV + ((size_t)q * TK_ + kt) * D_;
#pragma unroll
            for (int i = 0; i < 4; i++) {
                int idx = tid + i * 256;
                int k  = idx >> 4;
                int dc = (idx & 15) * 4;
                cp16(PVs + (s * 64 + k) * VSTR + dc, PVq + (size_t)k * D_ + dc);
            }
            CP_COMMIT();
        };

        const int wn = wid * 8;

        float c[2][4] = {};

        load_stage(0, 0);
        for (int ci = 0; ci < 16; ci++) {
            const int s = ci & 1;
            if (ci < 15) { load_stage(s ^ 1, (ci + 1) * 64); CP_WAIT1(); }
            else         { CP_WAIT0(); }
            __syncthreads();

#pragma unroll
            for (int k0 = 0; k0 < 64; k0 += 16) {
                u32 a[2][4], bh[2], bl[2];
#pragma unroll
                for (int mi = 0; mi < 2; mi++) {
                    const __half* ph = Ahs + (s * 32 + mi * 16 + g) * STRD + k0 + 2 * tg;
                    a[mi][0] = *(const u32*)(ph);
                    a[mi][1] = *(const u32*)(ph + 8 * STRD);
                    a[mi][2] = *(const u32*)(ph + 8);
                    a[mi][3] = *(const u32*)(ph + 8 * STRD + 8);
                }
                {
                    const int n = wn + g;
                    const int kb = k0 + 2 * tg;
                    split2h(PVs[(s * 64 + kb) * VSTR + n],
                            PVs[(s * 64 + kb + 1) * VSTR + n], bh[0], bl[0]);
                    split2h(PVs[(s * 64 + kb + 8) * VSTR + n],
                            PVs[(s * 64 + kb + 9) * VSTR + n], bh[1], bl[1]);
                }
#pragma unroll
                for (int mi = 0; mi < 2; mi++) {
                    mma_f16(c[mi], a[mi][0], a[mi][1], a[mi][2], a[mi][3], bh[0], bh[1]);
                    mma_f16(c[mi], a[mi][0], a[mi][1], a[mi][2], a[mi][3], bl[0], bl[1]);
                }
            }
            __syncthreads();
        }

#pragma unroll
        for (int mi = 0; mi < 2; mi++) {
            const int b0 = mi * 16 + g;
            const int b1 = b0 + 8;
            const int n  = wn + 2 * tg;
            float* d0 = g_O2 + ((size_t)b0 * TQ_ + q) * D_ + n;
            *(float2*)d0 = make_float2(c[mi][0] * invs[b0], c[mi][1] * invs[b0]);
            float* d1 = g_O2 + ((size_t)b1 * TQ_ + q) * D_ + n;
            *(float2*)d1 = make_float2(c[mi][2] * invs[b1], c[mi][3] * invs[b1]);
        }
    }
}

// ---------------------------------------------------------------------------
// Kernel E: Out += g_O2 (content + pos contributions). 2M floats.
// ---------------------------------------------------------------------------
extern "C" __global__ void __launch_bounds__(256)
add_kernel(float* __restrict__ Out)
{
    size_t idx = (size_t)blockIdx.x * 256 + threadIdx.x;
    float4 o = ((const float4*)Out)[idx];
    float4 a = ((const float4*)g_O2)[idx];
    o.x += a.x; o.y += a.y; o.z += a.z; o.w += a.w;
    ((float4*)Out)[idx] = o;
}

// ---------------------------------------------------------------------------
extern "C" void kernel_launch(void* const* d_in, const int* in_sizes, int n_in,
                              void* d_out, int out_size)
{
    const float* Q  = (const float*)d_in[0];
    const float* K  = (const float*)d_in[1];
    const float* V  = (const float*)d_in[2];
    const float* PK = (const float*)d_in[3];
    const float* PV = (const float*)d_in[4];
    const int*   VL = (const int*)d_in[5];
    float* Out = (float*)d_out;

    cudaFuncSetAttribute(qk_kernel, cudaFuncAttributeMaxDynamicSharedMemorySize,
                         QK_SMEM);
    cudaFuncSetAttribute(pvposv_kernel, cudaFuncAttributeMaxDynamicSharedMemorySize,
                         PV_SMEM);

    prep_qk_kernel<<<2048, 256>>>(Q, K);
    qk_kernel<<<dim3(TK_ / 64, TQ_ / 128, B_), 256, QK_SMEM>>>();
    posk_kernel<<<dim3(2, TQ_), 256>>>(PK, VL);
    pvposv_kernel<<<1536, 256, PV_SMEM>>>(V, PV, Out);
    add_kernel<<<2048, 256>>>(Out);
}

// round 15
// speedup vs baseline: 1.0567x; 1.0567x over previous
#include <cuda_runtime.h>
#include <cuda_bf16.h>
#include <cuda_fp16.h>
#include <math.h>

typedef unsigned u32;

#define B_  32
#define TQ_ 1024
#define TK_ 1024
#define D_  64
#define STRD 72   // smem row stride in 2B elems (64 data + 8 pad): conflict-free frags
#define VSTR 68   // fp32 tile row stride (conflict-free for split reads)

// scratch: fp16 scores/probs, 8-part rowsums, pos_v overlap accumulator,
// precomputed bf16 hi/lo Q,K
static __device__ __half g_S[(size_t)B_ * TQ_ * TK_];
static __device__ __half g_P[(size_t)B_ * TQ_ * TK_];
static __device__ float  g_psum[(size_t)B_ * TQ_ * 8];
static __device__ float  g_O2[(size_t)B_ * TQ_ * D_];
static __device__ __nv_bfloat16 g_Qh[(size_t)B_ * TQ_ * D_];
static __device__ __nv_bfloat16 g_Ql[(size_t)B_ * TQ_ * D_];
static __device__ __nv_bfloat16 g_Kh[(size_t)B_ * TK_ * D_];
static __device__ __nv_bfloat16 g_Kl[(size_t)B_ * TK_ * D_];

// ---- mma helpers ----------------------------------------------------------
__device__ __forceinline__ void mma_bf16(float c[4], u32 a0, u32 a1, u32 a2, u32 a3,
                                         u32 b0, u32 b1)
{
    asm volatile(
        "mma.sync.aligned.m16n8k16.row.col.f32.bf16.bf16.f32 "
        "{%0,%1,%2,%3},{%4,%5,%6,%7},{%8,%9},{%0,%1,%2,%3};\n"
        : "+f"(c[0]), "+f"(c[1]), "+f"(c[2]), "+f"(c[3])
        : "r"(a0), "r"(a1), "r"(a2), "r"(a3), "r"(b0), "r"(b1));
}
__device__ __forceinline__ void mma_f16(float c[4], u32 a0, u32 a1, u32 a2, u32 a3,
                                        u32 b0, u32 b1)
{
    asm volatile(
        "mma.sync.aligned.m16n8k16.row.col.f32.f16.f16.f32 "
        "{%0,%1,%2,%3},{%4,%5,%6,%7},{%8,%9},{%0,%1,%2,%3};\n"
        : "+f"(c[0]), "+f"(c[1]), "+f"(c[2]), "+f"(c[3])
        : "r"(a0), "r"(a1), "r"(a2), "r"(a3), "r"(b0), "r"(b1));
}

__device__ __forceinline__ u32 cvt2bf(float hi, float lo) {
    u32 r;
    asm("cvt.rn.bf16x2.f32 %0,%1,%2;" : "=r"(r) : "f"(hi), "f"(lo));
    return r;
}
// bf16 hi/lo split (x0 -> low half, x1 -> high half)
__device__ __forceinline__ void split2(float x0, float x1, u32& h, u32& l) {
    h = cvt2bf(x1, x0);
    float h0 = __uint_as_float(h << 16);
    float h1 = __uint_as_float(h & 0xffff0000u);
    l = cvt2bf(x1 - h1, x0 - h0);
}
// fp16 pack (hi only)
__device__ __forceinline__ u32 pack2h(float x0, float x1) {
    __half2 hh = __floats2half2_rn(x0, x1);
    return *(u32*)&hh;
}

// ---- cp.async helpers -----------------------------------------------------
__device__ __forceinline__ void cp16(void* dst_smem, const void* src) {
    u32 d = (u32)__cvta_generic_to_shared(dst_smem);
    asm volatile("cp.async.cg.shared.global [%0], [%1], 16;\n" :: "r"(d), "l"(src));
}
#define CP_COMMIT() asm volatile("cp.async.commit_group;\n" ::)
#define CP_WAIT1()  asm volatile("cp.async.wait_group 1;\n" ::)
#define CP_WAIT0()  asm volatile("cp.async.wait_group 0;\n" ::)

// ---------------------------------------------------------------------------
// Kernel P0: precompute bf16 hi/lo for Q and K (row-major, same layout)
// ---------------------------------------------------------------------------
extern "C" __global__ void __launch_bounds__(256)
prep_qk_kernel(const float* __restrict__ Q, const float* __restrict__ K)
{
    size_t idx = (size_t)blockIdx.x * 256 + threadIdx.x;
    float4 v = ((const float4*)Q)[idx];
    u32 h0, l0, h1, l1;
    split2(v.x, v.y, h0, l0); split2(v.z, v.w, h1, l1);
    ((uint2*)g_Qh)[idx] = make_uint2(h0, h1);
    ((uint2*)g_Ql)[idx] = make_uint2(l0, l1);
    float4 w = ((const float4*)K)[idx];
    split2(w.x, w.y, h0, l0); split2(w.z, w.w, h1, l1);
    ((uint2*)g_Kh)[idx] = make_uint2(h0, h1);
    ((uint2*)g_Kl)[idx] = make_uint2(l0, l1);
}

// ---------------------------------------------------------------------------
// Kernel A: S[b,q,k] = Q[b,q,:]·K[b,k,:] (unscaled, fp16 out). bf16x3 MMA.
// Block tile 128(q) x 64(k); warps 4(m) x 2(n); dynamic smem (55.3 KB).
// ---------------------------------------------------------------------------
#define QK_A_H   (128 * STRD)
#define QK_B_H   (64 * STRD)
#define QK_SMEM  ((2 * QK_A_H + 2 * QK_B_H) * 2)

extern "C" __global__ void __launch_bounds__(256)
qk_kernel()
{
    extern __shared__ char dynq[];
    __half* Ah = (__half*)dynq;                 // [128][STRD] (bf16 bits)
    __half* Al = Ah + QK_A_H;
    __half* Bh = Al + QK_A_H;                   // [64][STRD]
    __half* Bl = Bh + QK_B_H;

    const int bz = blockIdx.z;
    const int qt = blockIdx.y * 128;
    const int kt = blockIdx.x * 64;
    __half* Sb = g_S + (size_t)bz * TQ_ * TK_;

    const int tid = threadIdx.x;
    {
        const __nv_bfloat16* qh = g_Qh + ((size_t)bz * TQ_ + qt) * D_;
        const __nv_bfloat16* ql = g_Ql + ((size_t)bz * TQ_ + qt) * D_;
#pragma unroll
        for (int i = 0; i < 2; i++) {
            int idx = tid + i * 256;
            int row = idx >> 2;
            int c8  = (idx & 3) * 16;
            cp16(Ah + row * STRD + c8,     qh + row * D_ + c8);
            cp16(Ah + row * STRD + c8 + 8, qh + row * D_ + c8 + 8);
            cp16(Al + row * STRD + c8,     ql + row * D_ + c8);
            cp16(Al + row * STRD + c8 + 8, ql + row * D_ + c8 + 8);
        }
        const __nv_bfloat16* kh = g_Kh + ((size_t)bz * TK_ + kt) * D_;
        const __nv_bfloat16* kl = g_Kl + ((size_t)bz * TK_ + kt) * D_;
        {
            int row = tid >> 2;
            int c8  = (tid & 3) * 16;
            cp16(Bh + row * STRD + c8,     kh + row * D_ + c8);
            cp16(Bh + row * STRD + c8 + 8, kh + row * D_ + c8 + 8);
            cp16(Bl + row * STRD + c8,     kl + row * D_ + c8);
            cp16(Bl + row * STRD + c8 + 8, kl + row * D_ + c8 + 8);
        }
    }
    CP_COMMIT();
    CP_WAIT0();
    __syncthreads();

    const int wid = tid >> 5, lane = tid & 31;
    const int g = lane >> 2, tg = lane & 3;
    const int wm = (wid >> 1) * 32;
    const int wn = (wid & 1) * 32;

    float c[2][4][4] = {};

#pragma unroll
    for (int k0 = 0; k0 < 64; k0 += 16) {
        u32 ah[2][4], al[2][4], bh[4][2], bl[4][2];
#pragma unroll
        for (int mi = 0; mi < 2; mi++) {
            const __half* ph = Ah + (wm + mi * 16 + g) * STRD + k0 + 2 * tg;
            ah[mi][0] = *(const u32*)(ph);
            ah[mi][1] = *(const u32*)(ph + 8 * STRD);
            ah[mi][2] = *(const u32*)(ph + 8);
            ah[mi][3] = *(const u32*)(ph + 8 * STRD + 8);
            const __half* pl = Al + (wm + mi * 16 + g) * STRD + k0 + 2 * tg;
            al[mi][0] = *(const u32*)(pl);
            al[mi][1] = *(const u32*)(pl + 8 * STRD);
            al[mi][2] = *(const u32*)(pl + 8);
            al[mi][3] = *(const u32*)(pl + 8 * STRD + 8);
        }
#pragma unroll
        for (int ni = 0; ni < 4; ni++) {
            const __half* ph = Bh + (wn + ni * 8 + g) * STRD + k0 + 2 * tg;
            bh[ni][0] = *(const u32*)(ph);
            bh[ni][1] = *(const u32*)(ph + 8);
            const __half* pl = Bl + (wn + ni * 8 + g) * STRD + k0 + 2 * tg;
            bl[ni][0] = *(const u32*)(pl);
            bl[ni][1] = *(const u32*)(pl + 8);
        }
#pragma unroll
        for (int mi = 0; mi < 2; mi++)
#pragma unroll
            for (int ni = 0; ni < 4; ni++) {
                mma_bf16(c[mi][ni], ah[mi][0], ah[mi][1], ah[mi][2], ah[mi][3],
                         bh[ni][0], bh[ni][1]);
                mma_bf16(c[mi][ni], al[mi][0], al[mi][1], al[mi][2], al[mi][3],
                         bh[ni][0], bh[ni][1]);
                mma_bf16(c[mi][ni], ah[mi][0], ah[mi][1], ah[mi][2], ah[mi][3],
                         bl[ni][0], bl[ni][1]);
            }
    }

    __syncthreads();
    __half* Es = Ah;   // [128][STRD]
#pragma unroll
    for (int mi = 0; mi < 2; mi++)
#pragma unroll
        for (int ni = 0; ni < 4; ni++) {
            int ml = wm + mi * 16 + g;
            int nl = wn + ni * 8 + 2 * tg;
            *(__half2*)&Es[ml * STRD + nl] =
                __floats2half2_rn(c[mi][ni][0], c[mi][ni][1]);
            *(__half2*)&Es[(ml + 8) * STRD + nl] =
                __floats2half2_rn(c[mi][ni][2], c[mi][ni][3]);
        }
    __syncthreads();
#pragma unroll
    for (int i = 0; i < 4; i++) {
        int idx = tid + i * 256;
        int row = idx >> 3;
        int c8  = (idx & 7) * 8;
        uint4 v = *(const uint4*)&Es[row * STRD + c8];
        *(uint4*)&Sb[(size_t)(qt + row) * TK_ + kt + c8] = v;
    }
}

// ---------------------------------------------------------------------------
// Kernel B: P(fp16) = exp(mask((S + Q·pos_k)/8)); emits partial rowsums.
// (R13 form: grid (8,1024), coalesced staged epilogue.)
// ---------------------------------------------------------------------------
__device__ __forceinline__ int bswz(int n, int c) {
    return n * 64 + ((((c >> 2) ^ (n & 7)) << 2) | (c & 3));
}
#define CSTR 132

extern "C" __global__ void __launch_bounds__(256)
posk_kernel(const float* __restrict__ PK, const int* __restrict__ VL)
{
    const int q  = blockIdx.y;
    const int kt = blockIdx.x * 128;

    __shared__ __nv_bfloat16 Ah[32][STRD], Al[32][STRD];
    __shared__ float Bs[128 * 64];        // pos_k fp32 swizzled; reused as Cs
    __shared__ float rsum2[32];
    __shared__ int vls[B_];

    const int tid = threadIdx.x;
    {
        int row = tid >> 3;
        int c8  = (tid & 7) * 8;
        cp16(&Ah[row][c8], g_Qh + ((size_t)row * TQ_ + q) * D_ + c8);
        cp16(&Al[row][c8], g_Ql + ((size_t)row * TQ_ + q) * D_ + c8);
    }
    {
        const float* PKq = PK + ((size_t)q * TK_ + kt) * D_;
#pragma unroll
        for (int i = 0; i < 8; i++) {
            int idx = tid + i * 256;
            int row = idx >> 4;
            int c4  = idx & 15;
            cp16(&Bs[row * 64 + ((c4 ^ (row & 7)) << 2)], PKq + row * 64 + c4 * 4);
        }
    }
    CP_COMMIT();
    if (tid < B_) vls[tid] = VL[tid];
    CP_WAIT0();
    __syncthreads();

    const int wid = tid >> 5, lane = tid & 31;
    const int g = lane >> 2, tg = lane & 3;
    const int wn = wid * 16;

    float c[2][2][4] = {};

#pragma unroll
    for (int k0 = 0; k0 < 64; k0 += 16) {
        u32 ah[2][4], al[2][4], bh[2][2], bl[2][2];
#pragma unroll
        for (int mi = 0; mi < 2; mi++) {
            const __nv_bfloat16* ph = &Ah[mi * 16 + g][k0 + 2 * tg];
            ah[mi][0] = *(const u32*)(ph);
            ah[mi][1] = *(const u32*)(ph + 8 * STRD);
            ah[mi][2] = *(const u32*)(ph + 8);
            ah[mi][3] = *(const u32*)(ph + 8 * STRD + 8);
            const __nv_bfloat16* pl = &Al[mi * 16 + g][k0 + 2 * tg];
            al[mi][0] = *(const u32*)(pl);
            al[mi][1] = *(const u32*)(pl + 8 * STRD);
            al[mi][2] = *(const u32*)(pl + 8);
            al[mi][3] = *(const u32*)(pl + 8 * STRD + 8);
        }
#pragma unroll
        for (int ni = 0; ni < 2; ni++) {
            const int n = wn + ni * 8 + g;
            float2 v0 = *(const float2*)&Bs[bswz(n, k0 + 2 * tg)];
            split2(v0.x, v0.y, bh[ni][0], bl[ni][0]);
            float2 v1 = *(const float2*)&Bs[bswz(n, k0 + 2 * tg + 8)];
            split2(v1.x, v1.y, bh[ni][1], bl[ni][1]);
        }
#pragma unroll
        for (int mi = 0; mi < 2; mi++)
#pragma unroll
            for (int ni = 0; ni < 2; ni++) {
                mma_bf16(c[mi][ni], ah[mi][0], ah[mi][1], ah[mi][2], ah[mi][3],
                         bh[ni][0], bh[ni][1]);
                mma_bf16(c[mi][ni], al[mi][0], al[mi][1], al[mi][2], al[mi][3],
                         bh[ni][0], bh[ni][1]);
                mma_bf16(c[mi][ni], ah[mi][0], ah[mi][1], ah[mi][2], ah[mi][3],
                         bl[ni][0], bl[ni][1]);
            }
    }

    __syncthreads();
    float* Cs = Bs;   // [32][CSTR]
#pragma unroll
    for (int mi = 0; mi < 2; mi++)
#pragma unroll
        for (int ni = 0; ni < 2; ni++) {
            const int b0  = mi * 16 + g;
            const int col = wn + ni * 8 + 2 * tg;
            *(float2*)&Cs[b0 * CSTR + col] =
                make_float2(c[mi][ni][0], c[mi][ni][1]);
            *(float2*)&Cs[(b0 + 8) * CSTR + col] =
                make_float2(c[mi][ni][2], c[mi][ni][3]);
        }
    __syncthreads();

#pragma unroll
    for (int i = 0; i < 2; i++) {
        int idx = tid + i * 256;
        int row = idx >> 4;
        int c8  = (idx & 15) * 8;
        uint4 sv = *(const uint4*)&g_S[((size_t)row * TQ_ + q) * TK_ + kt + c8];
        const int vl = vls[row];
        uint4 out;
        float sum8 = 0.f;
#pragma unroll
        for (int j = 0; j < 4; j++) {
            u32 sraw = ((const u32*)&sv)[j];
            float2 s = __half22float2(*(__half2*)&sraw);
            float cva = Cs[row * CSTR + c8 + 2 * j];
            float cvb = Cs[row * CSTR + c8 + 2 * j + 1];
            int col = kt + c8 + 2 * j;
            float e0 = (col     < vl) ? __expf((s.x + cva) * 0.125f) : 0.f;
            float e1 = (col + 1 < vl) ? __expf((s.y + cvb) * 0.125f) : 0.f;
            __half2 hp = __floats2half2_rn(e0, e1);
            ((u32*)&out)[j] = *(u32*)&hp;
            float2 er = __half22float2(hp);
            sum8 += er.x + er.y;
        }
        *(uint4*)&g_P[((size_t)row * TQ_ + q) * TK_ + kt + c8] = out;
        float v = sum8;
        v += __shfl_xor_sync(0xffffffffu, v, 1);
        v += __shfl_xor_sync(0xffffffffu, v, 2);
        v += __shfl_xor_sync(0xffffffffu, v, 4);
        v += __shfl_xor_sync(0xffffffffu, v, 8);
        if ((lane & 15) == 0) rsum2[row] = v;
    }
    __syncthreads();
    if (tid < 32)
        g_psum[((size_t)tid * TQ_ + q) * 8 + blockIdx.x] = rsum2[tid];
}

// ---------------------------------------------------------------------------
// Kernel C: MERGED pv + posv. grid 1536, interleaved 1:2.
// V / pos_v consumed as fp16 (hi only — residual dropped; err ~1e-4).
// pv writes Out; posv writes g_O2 (race-free). Dynamic smem = 53.5 KB.
// ---------------------------------------------------------------------------
#define PV_AH_BYTES (2 * 64 * STRD * 2)
#define PV_VS_BYTES (2 * 64 * VSTR * 4)
#define PV_SMEM     (PV_AH_BYTES + PV_VS_BYTES + 64 * 4)

extern "C" __global__ void __launch_bounds__(256)
pvposv_kernel(const float* __restrict__ V, const float* __restrict__ PV,
              float* __restrict__ Out)
{
    extern __shared__ char dynbuf[];
    const int bid = blockIdx.x;
    const int third = bid / 3;
    const int rem   = bid % 3;
    const int tid = threadIdx.x;
    const int wid = tid >> 5, lane = tid & 31;
    const int g = lane >> 2, tg = lane & 3;

    if (rem == 0) {
        // ---------------- pv path ------------------------------------------
        __half* AhB  = (__half*)dynbuf;                       // [2][64][STRD]
        float*  VsB  = (float*)(dynbuf + PV_AH_BYTES);        // [2][64][VSTR]
        float*  invs = (float*)(dynbuf + PV_AH_BYTES + PV_VS_BYTES);

        const int bz = third >> 4;
        const int qt = (third & 15) * 64;
        const float* Vb = V + (size_t)bz * TK_ * D_;
        const __half* Pb = g_P + (size_t)bz * TQ_ * TK_;

        if (tid < 64) {
            const float* ps = &g_psum[((size_t)bz * TQ_ + qt + tid) * 8];
            float4 a = *(const float4*)ps;
            float4 b = *(const float4*)(ps + 4);
            invs[tid] = 1.0f / (((a.x + a.y) + (a.z + a.w)) + ((b.x + b.y) + (b.z + b.w)));
        }

        auto load_stage = [&](int s, int kt) {
            __half* A = AhB + s * 64 * STRD;
            float*  Vt = VsB + s * 64 * VSTR;
#pragma unroll
            for (int i = 0; i < 2; i++) {
                int idx = tid + i * 256;
                int r  = idx >> 3;
                int kc = (idx & 7) * 8;
                cp16(A + r * STRD + kc, Pb + (size_t)(qt + r) * TK_ + kt + kc);
            }
#pragma unroll
            for (int i = 0; i < 4; i++) {
                int idx = tid + i * 256;
                int k  = idx >> 4;
                int dc = (idx & 15) * 4;
                cp16(Vt + k * VSTR + dc, Vb + (size_t)(kt + k) * D_ + dc);
            }
            CP_COMMIT();
        };

        const int wm = (wid >> 2) * 32;
        const int wn = (wid & 3) * 16;

        float c[2][2][4] = {};

        load_stage(0, 0);
        for (int ci = 0; ci < 16; ci++) {
            const int s = ci & 1;
            if (ci < 15) { load_stage(s ^ 1, (ci + 1) * 64); CP_WAIT1(); }
            else         { CP_WAIT0(); }
            __syncthreads();

            const __half* A = AhB + s * 64 * STRD;
            const float*  Vt = VsB + s * 64 * VSTR;
#pragma unroll
            for (int k0 = 0; k0 < 64; k0 += 16) {
                u32 a[2][4], bh[2][2];
#pragma unroll
                for (int mi = 0; mi < 2; mi++) {
                    const __half* ph = A + (wm + mi * 16 + g) * STRD + k0 + 2 * tg;
                    a[mi][0] = *(const u32*)(ph);
                    a[mi][1] = *(const u32*)(ph + 8 * STRD);
                    a[mi][2] = *(const u32*)(ph + 8);
                    a[mi][3] = *(const u32*)(ph + 8 * STRD + 8);
                }
#pragma unroll
                for (int ni = 0; ni < 2; ni++) {
                    const int n = wn + ni * 8 + g;
                    const int kb = k0 + 2 * tg;
                    bh[ni][0] = pack2h(Vt[kb * VSTR + n],       Vt[(kb + 1) * VSTR + n]);
                    bh[ni][1] = pack2h(Vt[(kb + 8) * VSTR + n], Vt[(kb + 9) * VSTR + n]);
                }
#pragma unroll
                for (int mi = 0; mi < 2; mi++)
#pragma unroll
                    for (int ni = 0; ni < 2; ni++)
                        mma_f16(c[mi][ni], a[mi][0], a[mi][1], a[mi][2], a[mi][3],
                                bh[ni][0], bh[ni][1]);
            }
            __syncthreads();
        }

#pragma unroll
        for (int mi = 0; mi < 2; mi++)
#pragma unroll
            for (int ni = 0; ni < 2; ni++) {
                int m = wm + mi * 16 + g;
                int n = wn + ni * 8 + 2 * tg;
                float inv0 = invs[m], inv1 = invs[m + 8];
                float* d0 = Out + ((size_t)bz * TQ_ + qt + m) * D_ + n;
                *(float2*)d0 = make_float2(c[mi][ni][0] * inv0, c[mi][ni][1] * inv0);
                float* d1 = Out + ((size_t)bz * TQ_ + qt + m + 8) * D_ + n;
                *(float2*)d1 = make_float2(c[mi][ni][2] * inv1, c[mi][ni][3] * inv1);
            }
    } else {
        // ---------------- posv path ----------------------------------------
        const int q = third * 2 + (rem - 1);

        __half* Ahs  = (__half*)dynbuf;                       // [2][32][STRD]
        float*  PVs  = (float*)(dynbuf + 2 * 32 * STRD * 2);  // [2][64][VSTR]
        float*  invs = (float*)(dynbuf + 2 * 32 * STRD * 2 + 2 * 64 * VSTR * 4);

        if (tid < B_) {
            const float* ps = &g_psum[((size_t)tid * TQ_ + q) * 8];
            float4 a = *(const float4*)ps;
            float4 b = *(const float4*)(ps + 4);
            invs[tid] = 1.0f / (((a.x + a.y) + (a.z + a.w)) + ((b.x + b.y) + (b.z + b.w)));
        }

        auto load_stage = [&](int s, int kt) {
            {
                int bb = tid >> 3;
                int kc = (tid & 7) * 8;
                cp16(Ahs + (s * 32 + bb) * STRD + kc,
                     g_P + ((size_t)bb * TQ_ + q) * TK_ + kt + kc);
            }
            const float* PVq = PV + ((size_t)q * TK_ + kt) * D_;
#pragma unroll
            for (int i = 0; i < 4; i++) {
                int idx = tid + i * 256;
                int k  = idx >> 4;
                int dc = (idx & 15) * 4;
                cp16(PVs + (s * 64 + k) * VSTR + dc, PVq + (size_t)k * D_ + dc);
            }
            CP_COMMIT();
        };

        const int wn = wid * 8;

        float c[2][4] = {};

        load_stage(0, 0);
        for (int ci = 0; ci < 16; ci++) {
            const int s = ci & 1;
            if (ci < 15) { load_stage(s ^ 1, (ci + 1) * 64); CP_WAIT1(); }
            else         { CP_WAIT0(); }
            __syncthreads();

#pragma unroll
            for (int k0 = 0; k0 < 64; k0 += 16) {
                u32 a[2][4], bh[2];
#pragma unroll
                for (int mi = 0; mi < 2; mi++) {
                    const __half* ph = Ahs + (s * 32 + mi * 16 + g) * STRD + k0 + 2 * tg;
                    a[mi][0] = *(const u32*)(ph);
                    a[mi][1] = *(const u32*)(ph + 8 * STRD);
                    a[mi][2] = *(const u32*)(ph + 8);
                    a[mi][3] = *(const u32*)(ph + 8 * STRD + 8);
                }
                {
                    const int n = wn + g;
                    const int kb = k0 + 2 * tg;
                    bh[0] = pack2h(PVs[(s * 64 + kb) * VSTR + n],
                                   PVs[(s * 64 + kb + 1) * VSTR + n]);
                    bh[1] = pack2h(PVs[(s * 64 + kb + 8) * VSTR + n],
                                   PVs[(s * 64 + kb + 9) * VSTR + n]);
                }
#pragma unroll
                for (int mi = 0; mi < 2; mi++)
                    mma_f16(c[mi], a[mi][0], a[mi][1], a[mi][2], a[mi][3], bh[0], bh[1]);
            }
            __syncthreads();
        }

#pragma unroll
        for (int mi = 0; mi < 2; mi++) {
            const int b0 = mi * 16 + g;
            const int b1 = b0 + 8;
            const int n  = wn + 2 * tg;
            float* d0 = g_O2 + ((size_t)b0 * TQ_ + q) * D_ + n;
            *(float2*)d0 = make_float2(c[mi][0] * invs[b0], c[mi][1] * invs[b0]);
            float* d1 = g_O2 + ((size_t)b1 * TQ_ + q) * D_ + n;
            *(float2*)d1 = make_float2(c[mi][2] * invs[b1], c[mi][3] * invs[b1]);
        }
    }
}

// ---------------------------------------------------------------------------
// Kernel E: Out += g_O2 (content + pos contributions). 2M floats.
// ---------------------------------------------------------------------------
extern "C" __global__ void __launch_bounds__(256)
add_kernel(float* __restrict__ Out)
{
    size_t idx = (size_t)blockIdx.x * 256 + threadIdx.x;
    float4 o = ((const float4*)Out)[idx];
    float4 a = ((const float4*)g_O2)[idx];
    o.x += a.x; o.y += a.y; o.z += a.z; o.w += a.w;
    ((float4*)Out)[idx] = o;
}

// ---------------------------------------------------------------------------
extern "C" void kernel_launch(void* const* d_in, const int* in_sizes, int n_in,
                              void* d_out, int out_size)
{
    const float* Q  = (const float*)d_in[0];
    const float* K  = (const float*)d_in[1];
    const float* V  = (const float*)d_in[2];
    const float* PK = (const float*)d_in[3];
    const float* PV = (const float*)d_in[4];
    const int*   VL = (const int*)d_in[5];
    float* Out = (float*)d_out;

    cudaFuncSetAttribute(qk_kernel, cudaFuncAttributeMaxDynamicSharedMemorySize,
                         QK_SMEM);
    cudaFuncSetAttribute(pvposv_kernel, cudaFuncAttributeMaxDynamicSharedMemorySize,
                         PV_SMEM);

    prep_qk_kernel<<<2048, 256>>>(Q, K);
    qk_kernel<<<dim3(TK_ / 64, TQ_ / 128, B_), 256, QK_SMEM>>>();
    posk_kernel<<<dim3(TK_ / 128, TQ_), 256>>>(PK, VL);
    pvposv_kernel<<<1536, 256, PV_SMEM>>>(V, PV, Out);
    add_kernel<<<2048, 256>>>(Out);
}

// round 16
// speedup vs baseline: 1.0652x; 1.0080x over previous
#include <cuda_runtime.h>
#include <cuda_bf16.h>
#include <cuda_fp16.h>
#include <math.h>

typedef unsigned u32;

#define B_  32
#define TQ_ 1024
#define TK_ 1024
#define D_  64
#define STRD 72   // smem row stride in 2B elems (64 data + 8 pad): conflict-free frags
#define VSTR 68   // fp32 tile row stride (conflict-free for split reads)

// scratch: fp16 scores/probs, 8-part rowsums, pos_v overlap accumulator,
// precomputed bf16 hi/lo Q,K
static __device__ __half g_S[(size_t)B_ * TQ_ * TK_];
static __device__ __half g_P[(size_t)B_ * TQ_ * TK_];
static __device__ float  g_psum[(size_t)B_ * TQ_ * 8];
static __device__ float  g_O2[(size_t)B_ * TQ_ * D_];
static __device__ __nv_bfloat16 g_Qh[(size_t)B_ * TQ_ * D_];
static __device__ __nv_bfloat16 g_Ql[(size_t)B_ * TQ_ * D_];
static __device__ __nv_bfloat16 g_Kh[(size_t)B_ * TK_ * D_];
static __device__ __nv_bfloat16 g_Kl[(size_t)B_ * TK_ * D_];

// ---- mma helpers ----------------------------------------------------------
__device__ __forceinline__ void mma_bf16(float c[4], u32 a0, u32 a1, u32 a2, u32 a3,
                                         u32 b0, u32 b1)
{
    asm volatile(
        "mma.sync.aligned.m16n8k16.row.col.f32.bf16.bf16.f32 "
        "{%0,%1,%2,%3},{%4,%5,%6,%7},{%8,%9},{%0,%1,%2,%3};\n"
        : "+f"(c[0]), "+f"(c[1]), "+f"(c[2]), "+f"(c[3])
        : "r"(a0), "r"(a1), "r"(a2), "r"(a3), "r"(b0), "r"(b1));
}
__device__ __forceinline__ void mma_f16(float c[4], u32 a0, u32 a1, u32 a2, u32 a3,
                                        u32 b0, u32 b1)
{
    asm volatile(
        "mma.sync.aligned.m16n8k16.row.col.f32.f16.f16.f32 "
        "{%0,%1,%2,%3},{%4,%5,%6,%7},{%8,%9},{%0,%1,%2,%3};\n"
        : "+f"(c[0]), "+f"(c[1]), "+f"(c[2]), "+f"(c[3])
        : "r"(a0), "r"(a1), "r"(a2), "r"(a3), "r"(b0), "r"(b1));
}

__device__ __forceinline__ u32 cvt2bf(float hi, float lo) {
    u32 r;
    asm("cvt.rn.bf16x2.f32 %0,%1,%2;" : "=r"(r) : "f"(hi), "f"(lo));
    return r;
}
// bf16 hi/lo split (x0 -> low half, x1 -> high half)
__device__ __forceinline__ void split2(float x0, float x1, u32& h, u32& l) {
    h = cvt2bf(x1, x0);
    float h0 = __uint_as_float(h << 16);
    float h1 = __uint_as_float(h & 0xffff0000u);
    l = cvt2bf(x1 - h1, x0 - h0);
}
// fp16 pack (hi only)
__device__ __forceinline__ u32 pack2h(float x0, float x1) {
    __half2 hh = __floats2half2_rn(x0, x1);
    return *(u32*)&hh;
}

// ---- cp.async helpers -----------------------------------------------------
__device__ __forceinline__ void cp16(void* dst_smem, const void* src) {
    u32 d = (u32)__cvta_generic_to_shared(dst_smem);
    asm volatile("cp.async.cg.shared.global [%0], [%1], 16;\n" :: "r"(d), "l"(src));
}
#define CP_COMMIT() asm volatile("cp.async.commit_group;\n" ::)
#define CP_WAIT1()  asm volatile("cp.async.wait_group 1;\n" ::)
#define CP_WAIT0()  asm volatile("cp.async.wait_group 0;\n" ::)

// ---------------------------------------------------------------------------
// Kernel P0: precompute bf16 hi/lo for Q and K (row-major, same layout)
// ---------------------------------------------------------------------------
extern "C" __global__ void __launch_bounds__(256)
prep_qk_kernel(const float* __restrict__ Q, const float* __restrict__ K)
{
    size_t idx = (size_t)blockIdx.x * 256 + threadIdx.x;
    float4 v = ((const float4*)Q)[idx];
    u32 h0, l0, h1, l1;
    split2(v.x, v.y, h0, l0); split2(v.z, v.w, h1, l1);
    ((uint2*)g_Qh)[idx] = make_uint2(h0, h1);
    ((uint2*)g_Ql)[idx] = make_uint2(l0, l1);
    float4 w = ((const float4*)K)[idx];
    split2(w.x, w.y, h0, l0); split2(w.z, w.w, h1, l1);
    ((uint2*)g_Kh)[idx] = make_uint2(h0, h1);
    ((uint2*)g_Kl)[idx] = make_uint2(l0, l1);
}

// ---------------------------------------------------------------------------
// Kernel A: S[b,q,k] = Q[b,q,:]·K[b,k,:] (unscaled, fp16 out). bf16x3 MMA.
// Block tile 128(q) x 128(k); warps 4(m) x 2(n) of 32x64; dyn smem 72 KB.
// ---------------------------------------------------------------------------
#define QK_AB_H  (128 * STRD)
#define QK_SMEM  (4 * QK_AB_H * 2)
#define ESTR 136

extern "C" __global__ void __launch_bounds__(256)
qk_kernel()
{
    extern __shared__ char dynq[];
    __half* Ah = (__half*)dynq;                 // [128][STRD] (bf16 bits)
    __half* Al = Ah + QK_AB_H;
    __half* Bh = Al + QK_AB_H;                  // [128][STRD]
    __half* Bl = Bh + QK_AB_H;

    const int bz = blockIdx.z;
    const int qt = blockIdx.y * 128;
    const int kt = blockIdx.x * 128;
    __half* Sb = g_S + (size_t)bz * TQ_ * TK_;

    const int tid = threadIdx.x;
    {
        const __nv_bfloat16* qh = g_Qh + ((size_t)bz * TQ_ + qt) * D_;
        const __nv_bfloat16* ql = g_Ql + ((size_t)bz * TQ_ + qt) * D_;
        const __nv_bfloat16* kh = g_Kh + ((size_t)bz * TK_ + kt) * D_;
        const __nv_bfloat16* kl = g_Kl + ((size_t)bz * TK_ + kt) * D_;
#pragma unroll
        for (int i = 0; i < 4; i++) {           // 1024 chunks over 128 rows x 8
            int idx = tid + i * 256;
            int row = idx >> 3;
            int c8  = (idx & 7) * 8;
            cp16(Ah + row * STRD + c8, qh + row * D_ + c8);
            cp16(Al + row * STRD + c8, ql + row * D_ + c8);
            cp16(Bh + row * STRD + c8, kh + row * D_ + c8);
            cp16(Bl + row * STRD + c8, kl + row * D_ + c8);
        }
    }
    CP_COMMIT();
    CP_WAIT0();
    __syncthreads();

    const int wid = tid >> 5, lane = tid & 31;
    const int g = lane >> 2, tg = lane & 3;
    const int wm = (wid >> 1) * 32;             // 0,32,64,96
    const int wn = (wid & 1) * 64;              // 0,64

    float c[2][8][4] = {};

#pragma unroll
    for (int k0 = 0; k0 < 64; k0 += 16) {
        u32 ah[2][4], al[2][4];
#pragma unroll
        for (int mi = 0; mi < 2; mi++) {
            const __half* ph = Ah + (wm + mi * 16 + g) * STRD + k0 + 2 * tg;
            ah[mi][0] = *(const u32*)(ph);
            ah[mi][1] = *(const u32*)(ph + 8 * STRD);
            ah[mi][2] = *(const u32*)(ph + 8);
            ah[mi][3] = *(const u32*)(ph + 8 * STRD + 8);
            const __half* pl = Al + (wm + mi * 16 + g) * STRD + k0 + 2 * tg;
            al[mi][0] = *(const u32*)(pl);
            al[mi][1] = *(const u32*)(pl + 8 * STRD);
            al[mi][2] = *(const u32*)(pl + 8);
            al[mi][3] = *(const u32*)(pl + 8 * STRD + 8);
        }
#pragma unroll
        for (int ni = 0; ni < 8; ni++) {
            const __half* ph = Bh + (wn + ni * 8 + g) * STRD + k0 + 2 * tg;
            u32 b0 = *(const u32*)(ph);
            u32 b1 = *(const u32*)(ph + 8);
            const __half* pl = Bl + (wn + ni * 8 + g) * STRD + k0 + 2 * tg;
            u32 l0 = *(const u32*)(pl);
            u32 l1 = *(const u32*)(pl + 8);
#pragma unroll
            for (int mi = 0; mi < 2; mi++) {
                mma_bf16(c[mi][ni], ah[mi][0], ah[mi][1], ah[mi][2], ah[mi][3], b0, b1);
                mma_bf16(c[mi][ni], al[mi][0], al[mi][1], al[mi][2], al[mi][3], b0, b1);
                mma_bf16(c[mi][ni], ah[mi][0], ah[mi][1], ah[mi][2], ah[mi][3], l0, l1);
            }
        }
    }

    // stage to smem (overlays operand region; MMA fully consumed), coalesced
    __syncthreads();
    __half* Es = (__half*)dynq;   // [128][ESTR]
#pragma unroll
    for (int mi = 0; mi < 2; mi++)
#pragma unroll
        for (int ni = 0; ni < 8; ni++) {
            int ml = wm + mi * 16 + g;
            int nl = wn + ni * 8 + 2 * tg;
            *(__half2*)&Es[ml * ESTR + nl] =
                __floats2half2_rn(c[mi][ni][0], c[mi][ni][1]);
            *(__half2*)&Es[(ml + 8) * ESTR + nl] =
                __floats2half2_rn(c[mi][ni][2], c[mi][ni][3]);
        }
    __syncthreads();
#pragma unroll
    for (int i = 0; i < 8; i++) {
        int idx = tid + i * 256;                // 2048 chunks over 128x16
        int row = idx >> 4;
        int c8  = (idx & 15) * 8;
        uint4 v = *(const uint4*)&Es[row * ESTR + c8];
        *(uint4*)&Sb[(size_t)(qt + row) * TK_ + kt + c8] = v;
    }
}

// ---------------------------------------------------------------------------
// Kernel B: P(fp16) = exp(mask((S + Q·pos_k)/8)); emits partial rowsums.
// grid (8,1024). S tile prefetched via cp.async (2nd commit group).
// ---------------------------------------------------------------------------
__device__ __forceinline__ int bswz(int n, int c) {
    return n * 64 + ((((c >> 2) ^ (n & 7)) << 2) | (c & 3));
}
#define CSTR 132
#define SSTR 136

extern "C" __global__ void __launch_bounds__(256)
posk_kernel(const float* __restrict__ PK, const int* __restrict__ VL)
{
    const int q  = blockIdx.y;
    const int kt = blockIdx.x * 128;

    __shared__ __nv_bfloat16 Ah[32][STRD], Al[32][STRD];
    __shared__ float Bs[128 * 64];        // pos_k fp32 swizzled; reused as Cs
    __shared__ __half Ss[32][SSTR];       // prefetched S tile
    __shared__ float rsum2[32];
    __shared__ int vls[B_];

    const int tid = threadIdx.x;
    {
        int row = tid >> 3;
        int c8  = (tid & 7) * 8;
        cp16(&Ah[row][c8], g_Qh + ((size_t)row * TQ_ + q) * D_ + c8);
        cp16(&Al[row][c8], g_Ql + ((size_t)row * TQ_ + q) * D_ + c8);
    }
    {
        const float* PKq = PK + ((size_t)q * TK_ + kt) * D_;
#pragma unroll
        for (int i = 0; i < 8; i++) {
            int idx = tid + i * 256;
            int row = idx >> 4;
            int c4  = idx & 15;
            cp16(&Bs[row * 64 + ((c4 ^ (row & 7)) << 2)], PKq + row * 64 + c4 * 4);
        }
    }
    CP_COMMIT();                               // group A: operands
    {
#pragma unroll
        for (int i = 0; i < 2; i++) {          // 512 chunks over 32 rows x 16
            int idx = tid + i * 256;
            int row = idx >> 4;
            int c8  = (idx & 15) * 8;
            cp16(&Ss[row][c8], &g_S[((size_t)row * TQ_ + q) * TK_ + kt + c8]);
        }
    }
    CP_COMMIT();                               // group B: S tile
    if (tid < B_) vls[tid] = VL[tid];
    CP_WAIT1();                                // operands ready; S may fly on
    __syncthreads();

    const int wid = tid >> 5, lane = tid & 31;
    const int g = lane >> 2, tg = lane & 3;
    const int wn = wid * 16;

    float c[2][2][4] = {};

#pragma unroll
    for (int k0 = 0; k0 < 64; k0 += 16) {
        u32 ah[2][4], al[2][4], bh[2][2], bl[2][2];
#pragma unroll
        for (int mi = 0; mi < 2; mi++) {
            const __nv_bfloat16* ph = &Ah[mi * 16 + g][k0 + 2 * tg];
            ah[mi][0] = *(const u32*)(ph);
            ah[mi][1] = *(const u32*)(ph + 8 * STRD);
            ah[mi][2] = *(const u32*)(ph + 8);
            ah[mi][3] = *(const u32*)(ph + 8 * STRD + 8);
            const __nv_bfloat16* pl = &Al[mi * 16 + g][k0 + 2 * tg];
            al[mi][0] = *(const u32*)(pl);
            al[mi][1] = *(const u32*)(pl + 8 * STRD);
            al[mi][2] = *(const u32*)(pl + 8);
            al[mi][3] = *(const u32*)(pl + 8 * STRD + 8);
        }
#pragma unroll
        for (int ni = 0; ni < 2; ni++) {
            const int n = wn + ni * 8 + g;
            float2 v0 = *(const float2*)&Bs[bswz(n, k0 + 2 * tg)];
            split2(v0.x, v0.y, bh[ni][0], bl[ni][0]);
            float2 v1 = *(const float2*)&Bs[bswz(n, k0 + 2 * tg + 8)];
            split2(v1.x, v1.y, bh[ni][1], bl[ni][1]);
        }
#pragma unroll
        for (int mi = 0; mi < 2; mi++)
#pragma unroll
            for (int ni = 0; ni < 2; ni++) {
                mma_bf16(c[mi][ni], ah[mi][0], ah[mi][1], ah[mi][2], ah[mi][3],
                         bh[ni][0], bh[ni][1]);
                mma_bf16(c[mi][ni], al[mi][0], al[mi][1], al[mi][2], al[mi][3],
                         bh[ni][0], bh[ni][1]);
                mma_bf16(c[mi][ni], ah[mi][0], ah[mi][1], ah[mi][2], ah[mi][3],
                         bl[ni][0], bl[ni][1]);
            }
    }

    __syncthreads();
    float* Cs = Bs;   // [32][CSTR]
#pragma unroll
    for (int mi = 0; mi < 2; mi++)
#pragma unroll
        for (int ni = 0; ni < 2; ni++) {
            const int b0  = mi * 16 + g;
            const int col = wn + ni * 8 + 2 * tg;
            *(float2*)&Cs[b0 * CSTR + col] =
                make_float2(c[mi][ni][0], c[mi][ni][1]);
            *(float2*)&Cs[(b0 + 8) * CSTR + col] =
                make_float2(c[mi][ni][2], c[mi][ni][3]);
        }
    CP_WAIT0();                                // S tile landed
    __syncthreads();

#pragma unroll
    for (int i = 0; i < 2; i++) {
        int idx = tid + i * 256;
        int row = idx >> 4;
        int c8  = (idx & 15) * 8;
        uint4 sv = *(const uint4*)&Ss[row][c8];
        const int vl = vls[row];
        uint4 out;
        float sum8 = 0.f;
#pragma unroll
        for (int j = 0; j < 4; j++) {
            u32 sraw = ((const u32*)&sv)[j];
            float2 s = __half22float2(*(__half2*)&sraw);
            float cva = Cs[row * CSTR + c8 + 2 * j];
            float cvb = Cs[row * CSTR + c8 + 2 * j + 1];
            int col = kt + c8 + 2 * j;
            float e0 = (col     < vl) ? __expf((s.x + cva) * 0.125f) : 0.f;
            float e1 = (col + 1 < vl) ? __expf((s.y + cvb) * 0.125f) : 0.f;
            __half2 hp = __floats2half2_rn(e0, e1);
            ((u32*)&out)[j] = *(u32*)&hp;
            float2 er = __half22float2(hp);
            sum8 += er.x + er.y;
        }
        *(uint4*)&g_P[((size_t)row * TQ_ + q) * TK_ + kt + c8] = out;
        float v = sum8;
        v += __shfl_xor_sync(0xffffffffu, v, 1);
        v += __shfl_xor_sync(0xffffffffu, v, 2);
        v += __shfl_xor_sync(0xffffffffu, v, 4);
        v += __shfl_xor_sync(0xffffffffu, v, 8);
        if ((lane & 15) == 0) rsum2[row] = v;
    }
    __syncthreads();
    if (tid < 32)
        g_psum[((size_t)tid * TQ_ + q) * 8 + blockIdx.x] = rsum2[tid];
}

// ---------------------------------------------------------------------------
// Kernel C: MERGED pv + posv. grid 1536, interleaved 1:2.
// V / pos_v consumed as fp16 (hi only). pv writes Out; posv writes g_O2.
// ---------------------------------------------------------------------------
#define PV_AH_BYTES (2 * 64 * STRD * 2)
#define PV_VS_BYTES (2 * 64 * VSTR * 4)
#define PV_SMEM     (PV_AH_BYTES + PV_VS_BYTES + 64 * 4)

extern "C" __global__ void __launch_bounds__(256)
pvposv_kernel(const float* __restrict__ V, const float* __restrict__ PV,
              float* __restrict__ Out)
{
    extern __shared__ char dynbuf[];
    const int bid = blockIdx.x;
    const int third = bid / 3;
    const int rem   = bid % 3;
    const int tid = threadIdx.x;
    const int wid = tid >> 5, lane = tid & 31;
    const int g = lane >> 2, tg = lane & 3;

    if (rem == 0) {
        // ---------------- pv path ------------------------------------------
        __half* AhB  = (__half*)dynbuf;                       // [2][64][STRD]
        float*  VsB  = (float*)(dynbuf + PV_AH_BYTES);        // [2][64][VSTR]
        float*  invs = (float*)(dynbuf + PV_AH_BYTES + PV_VS_BYTES);

        const int bz = third >> 4;
        const int qt = (third & 15) * 64;
        const float* Vb = V + (size_t)bz * TK_ * D_;
        const __half* Pb = g_P + (size_t)bz * TQ_ * TK_;

        if (tid < 64) {
            const float* ps = &g_psum[((size_t)bz * TQ_ + qt + tid) * 8];
            float4 a = *(const float4*)ps;
            float4 b = *(const float4*)(ps + 4);
            invs[tid] = 1.0f / (((a.x + a.y) + (a.z + a.w)) + ((b.x + b.y) + (b.z + b.w)));
        }

        auto load_stage = [&](int s, int kt) {
            __half* A = AhB + s * 64 * STRD;
            float*  Vt = VsB + s * 64 * VSTR;
#pragma unroll
            for (int i = 0; i < 2; i++) {
                int idx = tid + i * 256;
                int r  = idx >> 3;
                int kc = (idx & 7) * 8;
                cp16(A + r * STRD + kc, Pb + (size_t)(qt + r) * TK_ + kt + kc);
            }
#pragma unroll
            for (int i = 0; i < 4; i++) {
                int idx = tid + i * 256;
                int k  = idx >> 4;
                int dc = (idx & 15) * 4;
                cp16(Vt + k * VSTR + dc, Vb + (size_t)(kt + k) * D_ + dc);
            }
            CP_COMMIT();
        };

        const int wm = (wid >> 2) * 32;
        const int wn = (wid & 3) * 16;

        float c[2][2][4] = {};

        load_stage(0, 0);
        for (int ci = 0; ci < 16; ci++) {
            const int s = ci & 1;
            if (ci < 15) { load_stage(s ^ 1, (ci + 1) * 64); CP_WAIT1(); }
            else         { CP_WAIT0(); }
            __syncthreads();

            const __half* A = AhB + s * 64 * STRD;
            const float*  Vt = VsB + s * 64 * VSTR;
#pragma unroll
            for (int k0 = 0; k0 < 64; k0 += 16) {
                u32 a[2][4], bh[2][2];
#pragma unroll
                for (int mi = 0; mi < 2; mi++) {
                    const __half* ph = A + (wm + mi * 16 + g) * STRD + k0 + 2 * tg;
                    a[mi][0] = *(const u32*)(ph);
                    a[mi][1] = *(const u32*)(ph + 8 * STRD);
                    a[mi][2] = *(const u32*)(ph + 8);
                    a[mi][3] = *(const u32*)(ph + 8 * STRD + 8);
                }
#pragma unroll
                for (int ni = 0; ni < 2; ni++) {
                    const int n = wn + ni * 8 + g;
                    const int kb = k0 + 2 * tg;
                    bh[ni][0] = pack2h(Vt[kb * VSTR + n],       Vt[(kb + 1) * VSTR + n]);
                    bh[ni][1] = pack2h(Vt[(kb + 8) * VSTR + n], Vt[(kb + 9) * VSTR + n]);
                }
#pragma unroll
                for (int mi = 0; mi < 2; mi++)
#pragma unroll
                    for (int ni = 0; ni < 2; ni++)
                        mma_f16(c[mi][ni], a[mi][0], a[mi][1], a[mi][2], a[mi][3],
                                bh[ni][0], bh[ni][1]);
            }
            __syncthreads();
        }

#pragma unroll
        for (int mi = 0; mi < 2; mi++)
#pragma unroll
            for (int ni = 0; ni < 2; ni++) {
                int m = wm + mi * 16 + g;
                int n = wn + ni * 8 + 2 * tg;
                float inv0 = invs[m], inv1 = invs[m + 8];
                float* d0 = Out + ((size_t)bz * TQ_ + qt + m) * D_ + n;
                *(float2*)d0 = make_float2(c[mi][ni][0] * inv0, c[mi][ni][1] * inv0);
                float* d1 = Out + ((size_t)bz * TQ_ + qt + m + 8) * D_ + n;
                *(float2*)d1 = make_float2(c[mi][ni][2] * inv1, c[mi][ni][3] * inv1);
            }
    } else {
        // ---------------- posv path ----------------------------------------
        const int q = third * 2 + (rem - 1);

        __half* Ahs  = (__half*)dynbuf;                       // [2][32][STRD]
        float*  PVs  = (float*)(dynbuf + 2 * 32 * STRD * 2);  // [2][64][VSTR]
        float*  invs = (float*)(dynbuf + 2 * 32 * STRD * 2 + 2 * 64 * VSTR * 4);

        if (tid < B_) {
            const float* ps = &g_psum[((size_t)tid * TQ_ + q) * 8];
            float4 a = *(const float4*)ps;
            float4 b = *(const float4*)(ps + 4);
            invs[tid] = 1.0f / (((a.x + a.y) + (a.z + a.w)) + ((b.x + b.y) + (b.z + b.w)));
        }

        auto load_stage = [&](int s, int kt) {
            {
                int bb = tid >> 3;
                int kc = (tid & 7) * 8;
                cp16(Ahs + (s * 32 + bb) * STRD + kc,
                     g_P + ((size_t)bb * TQ_ + q) * TK_ + kt + kc);
            }
            const float* PVq = PV + ((size_t)q * TK_ + kt) * D_;
#pragma unroll
            for (int i = 0; i < 4; i++) {
                int idx = tid + i * 256;
                int k  = idx >> 4;
                int dc = (idx & 15) * 4;
                cp16(PVs + (s * 64 + k) * VSTR + dc, PVq + (size_t)k * D_ + dc);
            }
            CP_COMMIT();
        };

        const int wn = wid * 8;

        float c[2][4] = {};

        load_stage(0, 0);
        for (int ci = 0; ci < 16; ci++) {
            const int s = ci & 1;
            if (ci < 15) { load_stage(s ^ 1, (ci + 1) * 64); CP_WAIT1(); }
            else         { CP_WAIT0(); }
            __syncthreads();

#pragma unroll
            for (int k0 = 0; k0 < 64; k0 += 16) {
                u32 a[2][4], bh[2];
#pragma unroll
                for (int mi = 0; mi < 2; mi++) {
                    const __half* ph = Ahs + (s * 32 + mi * 16 + g) * STRD + k0 + 2 * tg;
                    a[mi][0] = *(const u32*)(ph);
                    a[mi][1] = *(const u32*)(ph + 8 * STRD);
                    a[mi][2] = *(const u32*)(ph + 8);
                    a[mi][3] = *(const u32*)(ph + 8 * STRD + 8);
                }
                {
                    const int n = wn + g;
                    const int kb = k0 + 2 * tg;
                    bh[0] = pack2h(PVs[(s * 64 + kb) * VSTR + n],
                                   PVs[(s * 64 + kb + 1) * VSTR + n]);
                    bh[1] = pack2h(PVs[(s * 64 + kb + 8) * VSTR + n],
                                   PVs[(s * 64 + kb + 9) * VSTR + n]);
                }
#pragma unroll
                for (int mi = 0; mi < 2; mi++)
                    mma_f16(c[mi], a[mi][0], a[mi][1], a[mi][2], a[mi][3], bh[0], bh[1]);
            }
            __syncthreads();
        }

#pragma unroll
        for (int mi = 0; mi < 2; mi++) {
            const int b0 = mi * 16 + g;
            const int b1 = b0 + 8;
            const int n  = wn + 2 * tg;
            float* d0 = g_O2 + ((size_t)b0 * TQ_ + q) * D_ + n;
            *(float2*)d0 = make_float2(c[mi][0] * invs[b0], c[mi][1] * invs[b0]);
            float* d1 = g_O2 + ((size_t)b1 * TQ_ + q) * D_ + n;
            *(float2*)d1 = make_float2(c[mi][2] * invs[b1], c[mi][3] * invs[b1]);
        }
    }
}

// ---------------------------------------------------------------------------
// Kernel E: Out += g_O2 (content + pos contributions). 2M floats.
// ---------------------------------------------------------------------------
extern "C" __global__ void __launch_bounds__(256)
add_kernel(float* __restrict__ Out)
{
    size_t idx = (size_t)blockIdx.x * 256 + threadIdx.x;
    float4 o = ((const float4*)Out)[idx];
    float4 a = ((const float4*)g_O2)[idx];
    o.x += a.x; o.y += a.y; o.z += a.z; o.w += a.w;
    ((float4*)Out)[idx] = o;
}

// ---------------------------------------------------------------------------
extern "C" void kernel_launch(void* const* d_in, const int* in_sizes, int n_in,
                              void* d_out, int out_size)
{
    const float* Q  = (const float*)d_in[0];
    const float* K  = (const float*)d_in[1];
    const float* V  = (const float*)d_in[2];
    const float* PK = (const float*)d_in[3];
    const float* PV = (const float*)d_in[4];
    const int*   VL = (const int*)d_in[5];
    float* Out = (float*)d_out;

    cudaFuncSetAttribute(qk_kernel, cudaFuncAttributeMaxDynamicSharedMemorySize,
                         QK_SMEM);
    cudaFuncSetAttribute(pvposv_kernel, cudaFuncAttributeMaxDynamicSharedMemorySize,
                         PV_SMEM);

    prep_qk_kernel<<<2048, 256>>>(Q, K);
    qk_kernel<<<dim3(TK_ / 128, TQ_ / 128, B_), 256, QK_SMEM>>>();
    posk_kernel<<<dim3(TK_ / 128, TQ_), 256>>>(PK, VL);
    pvposv_kernel<<<1536, 256, PV_SMEM>>>(V, PV, Out);
    add_kernel<<<2048, 256>>>(Out);
}

// round 17
// speedup vs baseline: 1.0675x; 1.0022x over previous
#include <cuda_runtime.h>
#include <cuda_bf16.h>
#include <cuda_fp16.h>
#include <math.h>

typedef unsigned u32;

#define B_  32
#define TQ_ 1024
#define TK_ 1024
#define D_  64
#define STRD 72   // smem row stride in 2B elems (64 data + 8 pad): conflict-free frags
#define VSTR 68   // fp32 tile row stride (conflict-free for split reads)

// scratch: fp16 scores/probs, 8-part rowsums, pos_v overlap accumulator
static __device__ __half g_S[(size_t)B_ * TQ_ * TK_];
static __device__ __half g_P[(size_t)B_ * TQ_ * TK_];
static __device__ float  g_psum[(size_t)B_ * TQ_ * 8];
static __device__ float  g_O2[(size_t)B_ * TQ_ * D_];

// ---- mma helpers ----------------------------------------------------------
__device__ __forceinline__ void mma_bf16(float c[4], u32 a0, u32 a1, u32 a2, u32 a3,
                                         u32 b0, u32 b1)
{
    asm volatile(
        "mma.sync.aligned.m16n8k16.row.col.f32.bf16.bf16.f32 "
        "{%0,%1,%2,%3},{%4,%5,%6,%7},{%8,%9},{%0,%1,%2,%3};\n"
        : "+f"(c[0]), "+f"(c[1]), "+f"(c[2]), "+f"(c[3])
        : "r"(a0), "r"(a1), "r"(a2), "r"(a3), "r"(b0), "r"(b1));
}
__device__ __forceinline__ void mma_f16(float c[4], u32 a0, u32 a1, u32 a2, u32 a3,
                                        u32 b0, u32 b1)
{
    asm volatile(
        "mma.sync.aligned.m16n8k16.row.col.f32.f16.f16.f32 "
        "{%0,%1,%2,%3},{%4,%5,%6,%7},{%8,%9},{%0,%1,%2,%3};\n"
        : "+f"(c[0]), "+f"(c[1]), "+f"(c[2]), "+f"(c[3])
        : "r"(a0), "r"(a1), "r"(a2), "r"(a3), "r"(b0), "r"(b1));
}

__device__ __forceinline__ u32 cvt2bf(float hi, float lo) {
    u32 r;
    asm("cvt.rn.bf16x2.f32 %0,%1,%2;" : "=r"(r) : "f"(hi), "f"(lo));
    return r;
}
// bf16 hi/lo split (x0 -> low half, x1 -> high half)
__device__ __forceinline__ void split2(float x0, float x1, u32& h, u32& l) {
    h = cvt2bf(x1, x0);
    float h0 = __uint_as_float(h << 16);
    float h1 = __uint_as_float(h & 0xffff0000u);
    l = cvt2bf(x1 - h1, x0 - h0);
}
// fp16 pack (hi only)
__device__ __forceinline__ u32 pack2h(float x0, float x1) {
    __half2 hh = __floats2half2_rn(x0, x1);
    return *(u32*)&hh;
}

// ---- cp.async helpers -----------------------------------------------------
__device__ __forceinline__ void cp16(void* dst_smem, const void* src) {
    u32 d = (u32)__cvta_generic_to_shared(dst_smem);
    asm volatile("cp.async.cg.shared.global [%0], [%1], 16;\n" :: "r"(d), "l"(src));
}
#define CP_COMMIT() asm volatile("cp.async.commit_group;\n" ::)
#define CP_WAIT1()  asm volatile("cp.async.wait_group 1;\n" ::)
#define CP_WAIT0()  asm volatile("cp.async.wait_group 0;\n" ::)

// ---------------------------------------------------------------------------
// Kernel A: S[b,q,k] = Q[b,q,:]·K[b,k,:] (unscaled, fp16 out). bf16x3 MMA.
// Block tile 128(q) x 128(k); inline fp32->bf16 hi/lo split at fill.
// ---------------------------------------------------------------------------
#define QK_AB_H  (128 * STRD)
#define QK_SMEM  (4 * QK_AB_H * 2)
#define ESTR 136

extern "C" __global__ void __launch_bounds__(256)
qk_kernel(const float* __restrict__ Q, const float* __restrict__ K)
{
    extern __shared__ char dynq[];
    __half* Ah = (__half*)dynq;                 // [128][STRD] (bf16 bits)
    __half* Al = Ah + QK_AB_H;
    __half* Bh = Al + QK_AB_H;                  // [128][STRD]
    __half* Bl = Bh + QK_AB_H;

    const int bz = blockIdx.z;
    const int qt = blockIdx.y * 128;
    const int kt = blockIdx.x * 128;
    __half* Sb = g_S + (size_t)bz * TQ_ * TK_;

    const int tid = threadIdx.x;
    {
        const float* Qb = Q + ((size_t)bz * TQ_ + qt) * D_;
        const float* Kb = K + ((size_t)bz * TK_ + kt) * D_;
#pragma unroll
        for (int i = 0; i < 8; i++) {           // 2048 float4 over 128x64
            int idx = tid + i * 256;
            int row = idx >> 4;
            int col = (idx & 15) * 4;
            float4 v = *(const float4*)(Qb + (size_t)row * D_ + col);
            u32 h0, l0, h1, l1;
            split2(v.x, v.y, h0, l0); split2(v.z, v.w, h1, l1);
            *(uint2*)&Ah[row * STRD + col] = make_uint2(h0, h1);
            *(uint2*)&Al[row * STRD + col] = make_uint2(l0, l1);
            float4 w = *(const float4*)(Kb + (size_t)row * D_ + col);
            split2(w.x, w.y, h0, l0); split2(w.z, w.w, h1, l1);
            *(uint2*)&Bh[row * STRD + col] = make_uint2(h0, h1);
            *(uint2*)&Bl[row * STRD + col] = make_uint2(l0, l1);
        }
    }
    __syncthreads();

    const int wid = tid >> 5, lane = tid & 31;
    const int g = lane >> 2, tg = lane & 3;
    const int wm = (wid >> 1) * 32;             // 0,32,64,96
    const int wn = (wid & 1) * 64;              // 0,64

    float c[2][8][4] = {};

#pragma unroll
    for (int k0 = 0; k0 < 64; k0 += 16) {
        u32 ah[2][4], al[2][4];
#pragma unroll
        for (int mi = 0; mi < 2; mi++) {
            const __half* ph = Ah + (wm + mi * 16 + g) * STRD + k0 + 2 * tg;
            ah[mi][0] = *(const u32*)(ph);
            ah[mi][1] = *(const u32*)(ph + 8 * STRD);
            ah[mi][2] = *(const u32*)(ph + 8);
            ah[mi][3] = *(const u32*)(ph + 8 * STRD + 8);
            const __half* pl = Al + (wm + mi * 16 + g) * STRD + k0 + 2 * tg;
            al[mi][0] = *(const u32*)(pl);
            al[mi][1] = *(const u32*)(pl + 8 * STRD);
            al[mi][2] = *(const u32*)(pl + 8);
            al[mi][3] = *(const u32*)(pl + 8 * STRD + 8);
        }
#pragma unroll
        for (int ni = 0; ni < 8; ni++) {
            const __half* ph = Bh + (wn + ni * 8 + g) * STRD + k0 + 2 * tg;
            u32 b0 = *(const u32*)(ph);
            u32 b1 = *(const u32*)(ph + 8);
            const __half* pl = Bl + (wn + ni * 8 + g) * STRD + k0 + 2 * tg;
            u32 l0 = *(const u32*)(pl);
            u32 l1 = *(const u32*)(pl + 8);
#pragma unroll
            for (int mi = 0; mi < 2; mi++) {
                mma_bf16(c[mi][ni], ah[mi][0], ah[mi][1], ah[mi][2], ah[mi][3], b0, b1);
                mma_bf16(c[mi][ni], al[mi][0], al[mi][1], al[mi][2], al[mi][3], b0, b1);
                mma_bf16(c[mi][ni], ah[mi][0], ah[mi][1], ah[mi][2], ah[mi][3], l0, l1);
            }
        }
    }

    // stage to smem (overlays operand region; MMA fully consumed), coalesced
    __syncthreads();
    __half* Es = (__half*)dynq;   // [128][ESTR]
#pragma unroll
    for (int mi = 0; mi < 2; mi++)
#pragma unroll
        for (int ni = 0; ni < 8; ni++) {
            int ml = wm + mi * 16 + g;
            int nl = wn + ni * 8 + 2 * tg;
            *(__half2*)&Es[ml * ESTR + nl] =
                __floats2half2_rn(c[mi][ni][0], c[mi][ni][1]);
            *(__half2*)&Es[(ml + 8) * ESTR + nl] =
                __floats2half2_rn(c[mi][ni][2], c[mi][ni][3]);
        }
    __syncthreads();
#pragma unroll
    for (int i = 0; i < 8; i++) {
        int idx = tid + i * 256;                // 2048 chunks over 128x16
        int row = idx >> 4;
        int c8  = (idx & 15) * 8;
        uint4 v = *(const uint4*)&Es[row * ESTR + c8];
        *(uint4*)&Sb[(size_t)(qt + row) * TK_ + kt + c8] = v;
    }
}

// ---------------------------------------------------------------------------
// Kernel B: P(fp16) = exp(mask((S + Q·pos_k)/8)); emits partial rowsums.
// grid (8,1024). S tile prefetched via cp.async; Q split inline from fp32.
// ---------------------------------------------------------------------------
__device__ __forceinline__ int bswz(int n, int c) {
    return n * 64 + ((((c >> 2) ^ (n & 7)) << 2) | (c & 3));
}
#define CSTR 132
#define SSTR 136

extern "C" __global__ void __launch_bounds__(256)
posk_kernel(const float* __restrict__ Q, const float* __restrict__ PK,
            const int* __restrict__ VL)
{
    const int q  = blockIdx.y;
    const int kt = blockIdx.x * 128;

    __shared__ __nv_bfloat16 Ah[32][STRD], Al[32][STRD];
    __shared__ float Bs[128 * 64];        // pos_k fp32 swizzled; reused as Cs
    __shared__ __half Ss[32][SSTR];       // prefetched S tile
    __shared__ float rsum2[32];
    __shared__ int vls[B_];

    const int tid = threadIdx.x;
    {
        const float* PKq = PK + ((size_t)q * TK_ + kt) * D_;
#pragma unroll
        for (int i = 0; i < 8; i++) {
            int idx = tid + i * 256;
            int row = idx >> 4;
            int c4  = idx & 15;
            cp16(&Bs[row * 64 + ((c4 ^ (row & 7)) << 2)], PKq + row * 64 + c4 * 4);
        }
    }
    CP_COMMIT();                               // group A: pos_k
    {
#pragma unroll
        for (int i = 0; i < 2; i++) {          // 512 chunks over 32 rows x 16
            int idx = tid + i * 256;
            int row = idx >> 4;
            int c8  = (idx & 15) * 8;
            cp16(&Ss[row][c8], &g_S[((size_t)row * TQ_ + q) * TK_ + kt + c8]);
        }
    }
    CP_COMMIT();                               // group B: S tile
    // Q slab: raw fp32 load + inline split (same bytes as hi/lo pair)
    {
#pragma unroll
        for (int i = 0; i < 2; i++) {          // 512 float4 over 32x64
            int idx = tid + i * 256;
            int row = idx >> 4;
            int col = (idx & 15) * 4;
            float4 v = *(const float4*)(Q + ((size_t)row * TQ_ + q) * D_ + col);
            u32 h0, l0, h1, l1;
            split2(v.x, v.y, h0, l0); split2(v.z, v.w, h1, l1);
            *(uint2*)&Ah[row][col] = make_uint2(h0, h1);
            *(uint2*)&Al[row][col] = make_uint2(l0, l1);
        }
    }
    if (tid < B_) vls[tid] = VL[tid];
    CP_WAIT1();                                // pos_k ready; S may fly on
    __syncthreads();

    const int wid = tid >> 5, lane = tid & 31;
    const int g = lane >> 2, tg = lane & 3;
    const int wn = wid * 16;

    float c[2][2][4] = {};

#pragma unroll
    for (int k0 = 0; k0 < 64; k0 += 16) {
        u32 ah[2][4], al[2][4], bh[2][2], bl[2][2];
#pragma unroll
        for (int mi = 0; mi < 2; mi++) {
            const __nv_bfloat16* ph = &Ah[mi * 16 + g][k0 + 2 * tg];
            ah[mi][0] = *(const u32*)(ph);
            ah[mi][1] = *(const u32*)(ph + 8 * STRD);
            ah[mi][2] = *(const u32*)(ph + 8);
            ah[mi][3] = *(const u32*)(ph + 8 * STRD + 8);
            const __nv_bfloat16* pl = &Al[mi * 16 + g][k0 + 2 * tg];
            al[mi][0] = *(const u32*)(pl);
            al[mi][1] = *(const u32*)(pl + 8 * STRD);
            al[mi][2] = *(const u32*)(pl + 8);
            al[mi][3] = *(const u32*)(pl + 8 * STRD + 8);
        }
#pragma unroll
        for (int ni = 0; ni < 2; ni++) {
            const int n = wn + ni * 8 + g;
            float2 v0 = *(const float2*)&Bs[bswz(n, k0 + 2 * tg)];
            split2(v0.x, v0.y, bh[ni][0], bl[ni][0]);
            float2 v1 = *(const float2*)&Bs[bswz(n, k0 + 2 * tg + 8)];
            split2(v1.x, v1.y, bh[ni][1], bl[ni][1]);
        }
#pragma unroll
        for (int mi = 0; mi < 2; mi++)
#pragma unroll
            for (int ni = 0; ni < 2; ni++) {
                mma_bf16(c[mi][ni], ah[mi][0], ah[mi][1], ah[mi][2], ah[mi][3],
                         bh[ni][0], bh[ni][1]);
                mma_bf16(c[mi][ni], al[mi][0], al[mi][1], al[mi][2], al[mi][3],
                         bh[ni][0], bh[ni][1]);
                mma_bf16(c[mi][ni], ah[mi][0], ah[mi][1], ah[mi][2], ah[mi][3],
                         bl[ni][0], bl[ni][1]);
            }
    }

    __syncthreads();
    float* Cs = Bs;   // [32][CSTR]
#pragma unroll
    for (int mi = 0; mi < 2; mi++)
#pragma unroll
        for (int ni = 0; ni < 2; ni++) {
            const int b0  = mi * 16 + g;
            const int col = wn + ni * 8 + 2 * tg;
            *(float2*)&Cs[b0 * CSTR + col] =
                make_float2(c[mi][ni][0], c[mi][ni][1]);
            *(float2*)&Cs[(b0 + 8) * CSTR + col] =
                make_float2(c[mi][ni][2], c[mi][ni][3]);
        }
    CP_WAIT0();                                // S tile landed
    __syncthreads();

#pragma unroll
    for (int i = 0; i < 2; i++) {
        int idx = tid + i * 256;
        int row = idx >> 4;
        int c8  = (idx & 15) * 8;
        uint4 sv = *(const uint4*)&Ss[row][c8];
        const int vl = vls[row];
        uint4 out;
        float sum8 = 0.f;
#pragma unroll
        for (int j = 0; j < 4; j++) {
            u32 sraw = ((const u32*)&sv)[j];
            float2 s = __half22float2(*(__half2*)&sraw);
            float cva = Cs[row * CSTR + c8 + 2 * j];
            float cvb = Cs[row * CSTR + c8 + 2 * j + 1];
            int col = kt + c8 + 2 * j;
            float e0 = (col     < vl) ? __expf((s.x + cva) * 0.125f) : 0.f;
            float e1 = (col + 1 < vl) ? __expf((s.y + cvb) * 0.125f) : 0.f;
            __half2 hp = __floats2half2_rn(e0, e1);
            ((u32*)&out)[j] = *(u32*)&hp;
            float2 er = __half22float2(hp);
            sum8 += er.x + er.y;
        }
        *(uint4*)&g_P[((size_t)row * TQ_ + q) * TK_ + kt + c8] = out;
        float v = sum8;
        v += __shfl_xor_sync(0xffffffffu, v, 1);
        v += __shfl_xor_sync(0xffffffffu, v, 2);
        v += __shfl_xor_sync(0xffffffffu, v, 4);
        v += __shfl_xor_sync(0xffffffffu, v, 8);
        if ((lane & 15) == 0) rsum2[row] = v;
    }
    __syncthreads();
    if (tid < 32)
        g_psum[((size_t)tid * TQ_ + q) * 8 + blockIdx.x] = rsum2[tid];
}

// ---------------------------------------------------------------------------
// Kernel C: MERGED pv + posv. grid 1536, interleaved 1:2.
// V / pos_v consumed as fp16 (hi only). pv writes Out; posv writes g_O2.
// ---------------------------------------------------------------------------
#define PV_AH_BYTES (2 * 64 * STRD * 2)
#define PV_VS_BYTES (2 * 64 * VSTR * 4)
#define PV_SMEM     (PV_AH_BYTES + PV_VS_BYTES + 64 * 4)

extern "C" __global__ void __launch_bounds__(256)
pvposv_kernel(const float* __restrict__ V, const float* __restrict__ PV,
              float* __restrict__ Out)
{
    extern __shared__ char dynbuf[];
    const int bid = blockIdx.x;
    const int third = bid / 3;
    const int rem   = bid % 3;
    const int tid = threadIdx.x;
    const int wid = tid >> 5, lane = tid & 31;
    const int g = lane >> 2, tg = lane & 3;

    if (rem == 0) {
        // ---------------- pv path ------------------------------------------
        __half* AhB  = (__half*)dynbuf;                       // [2][64][STRD]
        float*  VsB  = (float*)(dynbuf + PV_AH_BYTES);        // [2][64][VSTR]
        float*  invs = (float*)(dynbuf + PV_AH_BYTES + PV_VS_BYTES);

        const int bz = third >> 4;
        const int qt = (third & 15) * 64;
        const float* Vb = V + (size_t)bz * TK_ * D_;
        const __half* Pb = g_P + (size_t)bz * TQ_ * TK_;

        if (tid < 64) {
            const float* ps = &g_psum[((size_t)bz * TQ_ + qt + tid) * 8];
            float4 a = *(const float4*)ps;
            float4 b = *(const float4*)(ps + 4);
            invs[tid] = 1.0f / (((a.x + a.y) + (a.z + a.w)) + ((b.x + b.y) + (b.z + b.w)));
        }

        auto load_stage = [&](int s, int kt) {
            __half* A = AhB + s * 64 * STRD;
            float*  Vt = VsB + s * 64 * VSTR;
#pragma unroll
            for (int i = 0; i < 2; i++) {
                int idx = tid + i * 256;
                int r  = idx >> 3;
                int kc = (idx & 7) * 8;
                cp16(A + r * STRD + kc, Pb + (size_t)(qt + r) * TK_ + kt + kc);
            }
#pragma unroll
            for (int i = 0; i < 4; i++) {
                int idx = tid + i * 256;
                int k  = idx >> 4;
                int dc = (idx & 15) * 4;
                cp16(Vt + k * VSTR + dc, Vb + (size_t)(kt + k) * D_ + dc);
            }
            CP_COMMIT();
        };

        const int wm = (wid >> 2) * 32;
        const int wn = (wid & 3) * 16;

        float c[2][2][4] = {};

        load_stage(0, 0);
        for (int ci = 0; ci < 16; ci++) {
            const int s = ci & 1;
            if (ci < 15) { load_stage(s ^ 1, (ci + 1) * 64); CP_WAIT1(); }
            else         { CP_WAIT0(); }
            __syncthreads();

            const __half* A = AhB + s * 64 * STRD;
            const float*  Vt = VsB + s * 64 * VSTR;
#pragma unroll
            for (int k0 = 0; k0 < 64; k0 += 16) {
                u32 a[2][4], bh[2][2];
#pragma unroll
                for (int mi = 0; mi < 2; mi++) {
                    const __half* ph = A + (wm + mi * 16 + g) * STRD + k0 + 2 * tg;
                    a[mi][0] = *(const u32*)(ph);
                    a[mi][1] = *(const u32*)(ph + 8 * STRD);
                    a[mi][2] = *(const u32*)(ph + 8);
                    a[mi][3] = *(const u32*)(ph + 8 * STRD + 8);
                }
#pragma unroll
                for (int ni = 0; ni < 2; ni++) {
                    const int n = wn + ni * 8 + g;
                    const int kb = k0 + 2 * tg;
                    bh[ni][0] = pack2h(Vt[kb * VSTR + n],       Vt[(kb + 1) * VSTR + n]);
                    bh[ni][1] = pack2h(Vt[(kb + 8) * VSTR + n], Vt[(kb + 9) * VSTR + n]);
                }
#pragma unroll
                for (int mi = 0; mi < 2; mi++)
#pragma unroll
                    for (int ni = 0; ni < 2; ni++)
                        mma_f16(c[mi][ni], a[mi][0], a[mi][1], a[mi][2], a[mi][3],
                                bh[ni][0], bh[ni][1]);
            }
            __syncthreads();
        }

#pragma unroll
        for (int mi = 0; mi < 2; mi++)
#pragma unroll
            for (int ni = 0; ni < 2; ni++) {
                int m = wm + mi * 16 + g;
                int n = wn + ni * 8 + 2 * tg;
                float inv0 = invs[m], inv1 = invs[m + 8];
                float* d0 = Out + ((size_t)bz * TQ_ + qt + m) * D_ + n;
                *(float2*)d0 = make_float2(c[mi][ni][0] * inv0, c[mi][ni][1] * inv0);
                float* d1 = Out + ((size_t)bz * TQ_ + qt + m + 8) * D_ + n;
                *(float2*)d1 = make_float2(c[mi][ni][2] * inv1, c[mi][ni][3] * inv1);
            }
    } else {
        // ---------------- posv path ----------------------------------------
        const int q = third * 2 + (rem - 1);

        __half* Ahs  = (__half*)dynbuf;                       // [2][32][STRD]
        float*  PVs  = (float*)(dynbuf + 2 * 32 * STRD * 2);  // [2][64][VSTR]
        float*  invs = (float*)(dynbuf + 2 * 32 * STRD * 2 + 2 * 64 * VSTR * 4);

        if (tid < B_) {
            const float* ps = &g_psum[((size_t)tid * TQ_ + q) * 8];
            float4 a = *(const float4*)ps;
            float4 b = *(const float4*)(ps + 4);
            invs[tid] = 1.0f / (((a.x + a.y) + (a.z + a.w)) + ((b.x + b.y) + (b.z + b.w)));
        }

        auto load_stage = [&](int s, int kt) {
            {
                int bb = tid >> 3;
                int kc = (tid & 7) * 8;
                cp16(Ahs + (s * 32 + bb) * STRD + kc,
                     g_P + ((size_t)bb * TQ_ + q) * TK_ + kt + kc);
            }
            const float* PVq = PV + ((size_t)q * TK_ + kt) * D_;
#pragma unroll
            for (int i = 0; i < 4; i++) {
                int idx = tid + i * 256;
                int k  = idx >> 4;
                int dc = (idx & 15) * 4;
                cp16(PVs + (s * 64 + k) * VSTR + dc, PVq + (size_t)k * D_ + dc);
            }
            CP_COMMIT();
        };

        const int wn = wid * 8;

        float c[2][4] = {};

        load_stage(0, 0);
        for (int ci = 0; ci < 16; ci++) {
            const int s = ci & 1;
            if (ci < 15) { load_stage(s ^ 1, (ci + 1) * 64); CP_WAIT1(); }
            else         { CP_WAIT0(); }
            __syncthreads();

#pragma unroll
            for (int k0 = 0; k0 < 64; k0 += 16) {
                u32 a[2][4], bh[2];
#pragma unroll
                for (int mi = 0; mi < 2; mi++) {
                    const __half* ph = Ahs + (s * 32 + mi * 16 + g) * STRD + k0 + 2 * tg;
                    a[mi][0] = *(const u32*)(ph);
                    a[mi][1] = *(const u32*)(ph + 8 * STRD);
                    a[mi][2] = *(const u32*)(ph + 8);
                    a[mi][3] = *(const u32*)(ph + 8 * STRD + 8);
                }
                {
                    const int n = wn + g;
                    const int kb = k0 + 2 * tg;
                    bh[0] = pack2h(PVs[(s * 64 + kb) * VSTR + n],
                                   PVs[(s * 64 + kb + 1) * VSTR + n]);
                    bh[1] = pack2h(PVs[(s * 64 + kb + 8) * VSTR + n],
                                   PVs[(s * 64 + kb + 9) * VSTR + n]);
                }
#pragma unroll
                for (int mi = 0; mi < 2; mi++)
                    mma_f16(c[mi], a[mi][0], a[mi][1], a[mi][2], a[mi][3], bh[0], bh[1]);
            }
            __syncthreads();
        }

#pragma unroll
        for (int mi = 0; mi < 2; mi++) {
            const int b0 = mi * 16 + g;
            const int b1 = b0 + 8;
            const int n  = wn + 2 * tg;
            float* d0 = g_O2 + ((size_t)b0 * TQ_ + q) * D_ + n;
            *(float2*)d0 = make_float2(c[mi][0] * invs[b0], c[mi][1] * invs[b0]);
            float* d1 = g_O2 + ((size_t)b1 * TQ_ + q) * D_ + n;
            *(float2*)d1 = make_float2(c[mi][2] * invs[b1], c[mi][3] * invs[b1]);
        }
    }
}

// ---------------------------------------------------------------------------
// Kernel E: Out += g_O2 (content + pos contributions). 2M floats.
// ---------------------------------------------------------------------------
extern "C" __global__ void __launch_bounds__(256)
add_kernel(float* __restrict__ Out)
{
    size_t idx = (size_t)blockIdx.x * 256 + threadIdx.x;
    float4 o = ((const float4*)Out)[idx];
    float4 a = ((const float4*)g_O2)[idx];
    o.x += a.x; o.y += a.y; o.z += a.z; o.w += a.w;
    ((float4*)Out)[idx] = o;
}

// ---------------------------------------------------------------------------
extern "C" void kernel_launch(void* const* d_in, const int* in_sizes, int n_in,
                              void* d_out, int out_size)
{
    const float* Q  = (const float*)d_in[0];
    const float* K  = (const float*)d_in[1];
    const float* V  = (const float*)d_in[2];
    const float* PK = (const float*)d_in[3];
    const float* PV = (const float*)d_in[4];
    const int*   VL = (const int*)d_in[5];
    float* Out = (float*)d_out;

    cudaFuncSetAttribute(qk_kernel, cudaFuncAttributeMaxDynamicSharedMemorySize,
                         QK_SMEM);
    cudaFuncSetAttribute(pvposv_kernel, cudaFuncAttributeMaxDynamicSharedMemorySize,
                         PV_SMEM);

    qk_kernel<<<dim3(TK_ / 128, TQ_ / 128, B_), 256, QK_SMEM>>>(Q, K);
    posk_kernel<<<dim3(TK_ / 128, TQ_), 256>>>(Q, PK, VL);
    pvposv_kernel<<<1536, 256, PV_SMEM>>>(V, PV, Out);
    add_kernel<<<2048, 256>>>(Out);
}